// round 1
// baseline (speedup 1.0000x reference)
#include <cuda_runtime.h>
#include <math.h>

// ---------------- problem constants ----------------
constexpr int CB   = 8;      // batch
constexpr int CN   = 1024;   // nodes
constexpr int CM   = 8;      // speakers
constexpr int CDIN = 1024;
constexpr int CHID = 256;
constexpr int CL   = 2;
constexpr int CNC  = 7;
constexpr int CNH  = 4;
constexpr int CDH  = 64;
#define NEGF  (-9e15f)
#define ALPHAF 0.1f

// ---------------- scratch (static device memory; allocation-free) ----------------
__device__ float g_H   [CB*CN*CHID];
__device__ float g_Hn  [CB*CN*CHID];
__device__ float g_P   [CB*CM*CHID];
__device__ float g_Pagg[CB*CM*CHID];
__device__ float g_Pl1 [CB*CN*CHID];
__device__ float g_h   [CB*CN*CHID];
__device__ float g_Agg [CB*CN*CHID];
__device__ float g_Q   [CB*CN*CHID];
__device__ float g_K   [CB*CN*CHID];
__device__ float g_V   [CB*CN*CHID];
__device__ float g_ctx [CB*CN*CHID];
__device__ float g_T   [CB*CN*CHID];
__device__ float g_att [(long)CB*CN*CN];          // GAT attention  (33.5 MB)
__device__ float g_sc  [(long)CB*CNH*CN*CN];      // MHA scores     (134 MB)
__device__ float g_e1  [CB*CN];
__device__ float g_e2  [CB*CN];
__device__ float g_rsc [2];

// ---------------- generic tiled SGEMM ----------------
// C[M,N] = act( scale * A[M,K] @ B + bias + Res ), B row-major [K,N] (TRANSB=0)
// or B row-major [N,K] used as B^T (TRANSB=1). Batched over blockIdx.z via strides.
template<int ACT, int TRANSB>
__global__ void sgemm(const float* __restrict__ A, const float* __restrict__ Bm,
                      const float* __restrict__ bias, const float* __restrict__ Res,
                      float* __restrict__ C,
                      int M, int N, int K,
                      long sA, long sB, long sC, float scale)
{
    __shared__ float As[16][68];
    __shared__ float Bs[16][68];
    int bz = blockIdx.z;
    A  += (long)bz * sA;
    Bm += (long)bz * sB;
    C  += (long)bz * sC;

    int tx = threadIdx.x;                 // 0..255
    int tr = tx >> 4, tc = tx & 15;
    int row0 = blockIdx.y * 64, col0 = blockIdx.x * 64;

    float acc[4][4] = {};
    for (int k0 = 0; k0 < K; k0 += 16) {
        #pragma unroll
        for (int i = 0; i < 4; i++) {
            int idx = tx * 4 + i;               // 0..1023
            int m = idx >> 4, k = idx & 15;     // A tile: 64 rows x 16 k
            int gr = row0 + m;
            As[k][m] = (gr < M) ? A[(long)gr * K + k0 + k] : 0.f;
        }
        #pragma unroll
        for (int i = 0; i < 4; i++) {
            int idx = tx * 4 + i;
            if (TRANSB) {
                int n = idx >> 4, k = idx & 15;
                int gn = col0 + n;
                Bs[k][n] = (gn < N) ? Bm[(long)gn * K + k0 + k] : 0.f;
            } else {
                int k = idx >> 6, n = idx & 63;
                int gn = col0 + n;
                Bs[k][n] = (gn < N) ? Bm[(long)(k0 + k) * N + gn] : 0.f;
            }
        }
        __syncthreads();
        #pragma unroll
        for (int k = 0; k < 16; k++) {
            float a[4], b[4];
            #pragma unroll
            for (int i = 0; i < 4; i++) a[i] = As[k][tr * 4 + i];
            #pragma unroll
            for (int j = 0; j < 4; j++) b[j] = Bs[k][tc * 4 + j];
            #pragma unroll
            for (int i = 0; i < 4; i++)
                #pragma unroll
                for (int j = 0; j < 4; j++)
                    acc[i][j] = fmaf(a[i], b[j], acc[i][j]);
        }
        __syncthreads();
    }
    #pragma unroll
    for (int i = 0; i < 4; i++) {
        int gr = row0 + tr * 4 + i;
        if (gr >= M) continue;
        #pragma unroll
        for (int j = 0; j < 4; j++) {
            int gn = col0 + tc * 4 + j;
            if (gn >= N) continue;
            float v = acc[i][j] * scale;
            if (bias) v += bias[gn];
            if (Res)  v += Res[(long)bz * sC + (long)gr * N + gn];
            if (ACT == 1) v = v > 0.f ? v : 0.f;                    // relu
            else if (ACT == 2) v = v > 0.f ? v : expm1f(v);         // elu
            C[(long)gr * N + gn] = v;
        }
    }
}

// ---------------- P_l_1[b,n,d] = sum_m s_adj[b,m,n] * P[b,m,d] ----------------
__global__ void pl1_kernel(const float* __restrict__ sadj, const float* __restrict__ P,
                           float* __restrict__ out)
{
    long idx = (long)blockIdx.x * 256 + threadIdx.x;   // B*N*HID = 2M
    int d = idx & (CHID - 1);
    int n = (idx >> 8) & (CN - 1);
    int b = (int)(idx >> 18);
    const float* sa = sadj + (long)b * CM * CN + n;
    const float* Pb = P + (long)b * CM * CHID + d;
    float acc = 0.f;
    #pragma unroll
    for (int m = 0; m < CM; m++) acc = fmaf(sa[m * CN], Pb[m * CHID], acc);
    out[idx] = acc;
}

// ---------------- P_agg[b,m,d] = sum_n s_adj[b,m,n] * H[b,n,d] ----------------
__global__ void pagg_kernel(const float* __restrict__ sadj, const float* __restrict__ H,
                            float* __restrict__ out)
{
    int bm = blockIdx.x;                 // 0..63
    int b = bm >> 3;
    int d = threadIdx.x;
    const float* sa = sadj + (long)bm * CN;
    const float* Hb = H + (long)b * CN * CHID + d;
    float acc = 0.f;
    #pragma unroll 4
    for (int n = 0; n < CN; n++) acc = fmaf(sa[n], Hb[(long)n * CHID], acc);
    out[(long)bm * CHID + d] = acc;
}

// ---------------- e1/e2: per-row dots of h with a1, a2 ----------------
__global__ void dots_kernel(const float* __restrict__ h, const float* __restrict__ a1,
                            const float* __restrict__ a2,
                            float* __restrict__ e1, float* __restrict__ e2)
{
    __shared__ float s1[256], s2[256];
    int row = blockIdx.x, t = threadIdx.x;
    float v = h[(long)row * CHID + t];
    s1[t] = v * a1[t];
    s2[t] = v * a2[t];
    __syncthreads();
    for (int o = 128; o > 0; o >>= 1) {
        if (t < o) { s1[t] += s1[t + o]; s2[t] += s2[t + o]; }
        __syncthreads();
    }
    if (t == 0) { e1[row] = s1[0]; e2[row] = s2[0]; }
}

// ---------------- rel_sc[r] = dot(rel_emb[l][r], a3) ----------------
__global__ void relsc_kernel(const float* __restrict__ rel, const float* __restrict__ a3,
                             float* __restrict__ out)
{
    __shared__ float s[256];
    int r = blockIdx.x, t = threadIdx.x;
    s[t] = rel[r * CHID + t] * a3[t];
    __syncthreads();
    for (int o = 128; o > 0; o >>= 1) {
        if (t < o) s[t] += s[t + o];
        __syncthreads();
    }
    if (t == 0) out[r] = s[0];
}

// ---------------- GAT edge scores + masked softmax, one row per block ----------------
__global__ void gat_att_kernel(const float* __restrict__ e1, const float* __restrict__ e2,
                               const float* __restrict__ rsc,
                               const int* __restrict__ adj, const int* __restrict__ smask,
                               float* __restrict__ att)
{
    __shared__ float red[256];
    int bi = blockIdx.x;                 // b*N + i
    int b = bi >> 10;
    long base = (long)bi * CN;
    int t = threadIdx.x;
    float E1 = e1[bi];
    const float* e2b = e2 + b * CN;

    float vals[4];
    float mx = -3.4e38f;
    #pragma unroll
    for (int q = 0; q < 4; q++) {
        int j = t + q * 256;
        float e = E1 + e2b[j] + rsc[smask[base + j]];
        e = e >= 0.f ? e : ALPHAF * e;
        e = (adj[base + j] > 0) ? e : NEGF;
        vals[q] = e;
        mx = fmaxf(mx, e);
    }
    red[t] = mx; __syncthreads();
    for (int o = 128; o > 0; o >>= 1) {
        if (t < o) red[t] = fmaxf(red[t], red[t + o]);
        __syncthreads();
    }
    mx = red[0]; __syncthreads();
    float s = 0.f;
    #pragma unroll
    for (int q = 0; q < 4; q++) { vals[q] = expf(vals[q] - mx); s += vals[q]; }
    red[t] = s; __syncthreads();
    for (int o = 128; o > 0; o >>= 1) {
        if (t < o) red[t] += red[t + o];
        __syncthreads();
    }
    float inv = 1.f / red[0];
    #pragma unroll
    for (int q = 0; q < 4; q++) att[base + t + q * 256] = vals[q] * inv;
}

// ---------------- in-place row softmax over 1024 ----------------
__global__ void softmax1024(float* __restrict__ S)
{
    __shared__ float red[256];
    long base = (long)blockIdx.x * CN;
    int t = threadIdx.x;
    float vals[4];
    float mx = -3.4e38f;
    #pragma unroll
    for (int q = 0; q < 4; q++) { vals[q] = S[base + t + q * 256]; mx = fmaxf(mx, vals[q]); }
    red[t] = mx; __syncthreads();
    for (int o = 128; o > 0; o >>= 1) {
        if (t < o) red[t] = fmaxf(red[t], red[t + o]);
        __syncthreads();
    }
    mx = red[0]; __syncthreads();
    float s = 0.f;
    #pragma unroll
    for (int q = 0; q < 4; q++) { vals[q] = expf(vals[q] - mx); s += vals[q]; }
    red[t] = s; __syncthreads();
    for (int o = 128; o > 0; o >>= 1) {
        if (t < o) red[t] += red[t + o];
        __syncthreads();
    }
    float inv = 1.f / red[0];
    #pragma unroll
    for (int q = 0; q < 4; q++) S[base + t + q * 256] = vals[q] * inv;
}

// ---------------- LayerNorm( T + Hold ) * g + b ----------------
__global__ void ln_kernel(const float* __restrict__ T, const float* __restrict__ Hold,
                          const float* __restrict__ g, const float* __restrict__ bb,
                          float* __restrict__ out)
{
    __shared__ float red[256];
    int row = blockIdx.x, t = threadIdx.x;
    long off = (long)row * CHID + t;
    float v = T[off] + Hold[off];
    red[t] = v; __syncthreads();
    for (int o = 128; o > 0; o >>= 1) {
        if (t < o) red[t] += red[t + o];
        __syncthreads();
    }
    float mu = red[0] * (1.f / CHID);
    __syncthreads();
    float dv = v - mu;
    red[t] = dv * dv; __syncthreads();
    for (int o = 128; o > 0; o >>= 1) {
        if (t < o) red[t] += red[t + o];
        __syncthreads();
    }
    float var = red[0] * (1.f / CHID);
    out[off] = dv * rsqrtf(var + 1e-5f) * g[t] + bb[t];
}

// ---------------- GRU3d: in-place update of P (one row per block) ----------------
__global__ void gru_kernel(float* __restrict__ P, const float* __restrict__ Pagg,
                           const float* __restrict__ wz, const float* __restrict__ uz,
                           const float* __restrict__ wr, const float* __restrict__ ur,
                           const float* __restrict__ w,  const float* __restrict__ u)
{
    __shared__ float sp[CHID], sq[CHID];
    int r = blockIdx.x;                  // 0..63
    int c = threadIdx.x;
    sp[c] = P[(long)r * CHID + c];
    sq[c] = Pagg[(long)r * CHID + c];
    __syncthreads();
    float az = 0, bz = 0, ar = 0, br = 0, aw = 0, bw = 0;
    for (int k = 0; k < CHID; k++) {
        float pk = sp[k], qk = sq[k];
        az = fmaf(pk, wz[k * CHID + c], az); bz = fmaf(qk, uz[k * CHID + c], bz);
        ar = fmaf(pk, wr[k * CHID + c], ar); br = fmaf(qk, ur[k * CHID + c], br);
        aw = fmaf(pk, w [k * CHID + c], aw); bw = fmaf(qk, u [k * CHID + c], bw);
    }
    float z  = 1.f / (1.f + expf(-(az + bz)));
    float rr = 1.f / (1.f + expf(-(ar + br)));
    float hh = tanhf(aw + rr * bw);
    P[(long)r * CHID + c] = (1.f - z) * sp[c] + z * hh;
}

// ---------------- p_sim ----------------
__global__ void psim_kernel(const float* __restrict__ P, float* __restrict__ outp, int tail)
{
    __shared__ float red[64];
    int t = threadIdx.x;                 // b*M + m
    int b = t >> 3, m = t & 7;
    const float* Pb = P + (long)b * CM * CHID;
    float s = 0.f;
    for (int k2 = 0; k2 < CM; k2++) {
        if (k2 == m) continue;
        float d = 0.f;
        for (int dd = 0; dd < CHID; dd++)
            d = fmaf(Pb[m * CHID + dd], Pb[k2 * CHID + dd], d);
        s += d;
    }
    red[t] = s; __syncthreads();
    if ((t & 7) < 4) red[t] += red[t + 4]; __syncthreads();
    if ((t & 7) < 2) red[t] += red[t + 2]; __syncthreads();
    if ((t & 7) < 1) red[t] += red[t + 1]; __syncthreads();
    if (tail >= CB) {
        if (t < CB) outp[t] = red[t * 8] / (float)(CM * CM);
    } else {
        if (t == 0) {
            float tot = 0.f;
            for (int b2 = 0; b2 < CB; b2++) tot += red[b2 * 8];
            outp[0] = tot / (float)(CB * CM * CM);
        }
    }
}

// ---------------- host orchestration ----------------
extern "C" void kernel_launch(void* const* d_in, const int* in_sizes, int n_in,
                              void* d_out, int out_size)
{
    const float* x     = (const float*)d_in[0];
    const int*   adj   = (const int*)  d_in[1];
    const int*   smask = (const int*)  d_in[2];
    const float* sf    = (const float*)d_in[3];
    const float* sadj  = (const float*)d_in[4];
    const float* fc1w  = (const float*)d_in[6];
    const float* fc1b  = (const float*)d_in[7];
    const float* fc2w  = (const float*)d_in[8];
    const float* fc2b  = (const float*)d_in[9];
    const float* gatW  = (const float*)d_in[10];
    const float* gata  = (const float*)d_in[11];
    const float* rel   = (const float*)d_in[12];
    const float* gwz   = (const float*)d_in[13];
    const float* guz   = (const float*)d_in[14];
    const float* gwr   = (const float*)d_in[15];
    const float* gur   = (const float*)d_in[16];
    const float* gw    = (const float*)d_in[17];
    const float* gu    = (const float*)d_in[18];
    const float* wv    = (const float*)d_in[19];
    const float* bv    = (const float*)d_in[20];
    const float* wk    = (const float*)d_in[21];
    const float* bk    = (const float*)d_in[22];
    const float* wq    = (const float*)d_in[23];
    const float* bq    = (const float*)d_in[24];
    const float* wo    = (const float*)d_in[25];
    const float* bo    = (const float*)d_in[26];
    const float* lng   = (const float*)d_in[27];
    const float* lnb   = (const float*)d_in[28];
    const float* outw  = (const float*)d_in[29];
    const float* outb  = (const float*)d_in[30];
    float* out = (float*)d_out;

    float *H, *Hn, *P, *Pagg, *Pl1, *hb, *Agg, *Qb, *Kb, *Vb, *ctx, *Tb, *att, *sc, *e1, *e2, *rsc;
    cudaGetSymbolAddress((void**)&H,    g_H);
    cudaGetSymbolAddress((void**)&Hn,   g_Hn);
    cudaGetSymbolAddress((void**)&P,    g_P);
    cudaGetSymbolAddress((void**)&Pagg, g_Pagg);
    cudaGetSymbolAddress((void**)&Pl1,  g_Pl1);
    cudaGetSymbolAddress((void**)&hb,   g_h);
    cudaGetSymbolAddress((void**)&Agg,  g_Agg);
    cudaGetSymbolAddress((void**)&Qb,   g_Q);
    cudaGetSymbolAddress((void**)&Kb,   g_K);
    cudaGetSymbolAddress((void**)&Vb,   g_V);
    cudaGetSymbolAddress((void**)&ctx,  g_ctx);
    cudaGetSymbolAddress((void**)&Tb,   g_T);
    cudaGetSymbolAddress((void**)&att,  g_att);
    cudaGetSymbolAddress((void**)&sc,   g_sc);
    cudaGetSymbolAddress((void**)&e1,   g_e1);
    cudaGetSymbolAddress((void**)&e2,   g_e2);
    cudaGetSymbolAddress((void**)&rsc,  g_rsc);

    dim3 blk(256);
    const int BN = CB * CN;                          // 8192
    const long HH = (long)CHID * CHID;               // 65536

    // H = relu(x @ fc1_w + b);  P = relu(s_feature @ fc2_w + b)
    sgemm<1, 0><<<dim3(4, 128, 1), blk>>>(x,  fc1w, fc1b, nullptr, H, BN, CHID, CDIN, 0, 0, 0, 1.f);
    sgemm<1, 0><<<dim3(4, 1, 1),   blk>>>(sf, fc2w, fc2b, nullptr, P, CB * CM, CHID, CDIN, 0, 0, 0, 1.f);

    for (int l = 0; l < CL; l++) {
        float* cur = l ? Hn : H;
        float* nxt = l ? H : Hn;

        // P_l_1 = s_adj^T @ P
        pl1_kernel<<<BN * CHID / 256, blk>>>(sadj, P, Pl1);

        // h = H @ gat_W[l]
        sgemm<0, 0><<<dim3(4, 128, 1), blk>>>(cur, gatW + l * HH, nullptr, nullptr, hb,
                                              BN, CHID, CHID, 0, 0, 0, 1.f);
        // edge-score ingredients
        dots_kernel<<<BN, blk>>>(hb, gata + l * 3 * CHID, gata + l * 3 * CHID + CHID, e1, e2);
        relsc_kernel<<<2, blk>>>(rel + l * 2 * CHID, gata + l * 3 * CHID + 2 * CHID, rsc);
        // masked softmax rows of att
        gat_att_kernel<<<BN, blk>>>(e1, e2, rsc, adj, smask, att);
        // Agg = elu(att @ h)   (batched over b)
        sgemm<2, 0><<<dim3(4, 16, CB), blk>>>(att, hb, nullptr, nullptr, Agg,
                                              CN, CHID, CN,
                                              (long)CN * CN, (long)CN * CHID, (long)CN * CHID, 1.f);
        // projections
        sgemm<0, 0><<<dim3(4, 128, 1), blk>>>(cur, wv + l * HH, bv + l * CHID, nullptr, Vb,
                                              BN, CHID, CHID, 0, 0, 0, 1.f);
        sgemm<0, 0><<<dim3(4, 128, 1), blk>>>(Pl1, wk + l * HH, bk + l * CHID, nullptr, Kb,
                                              BN, CHID, CHID, 0, 0, 0, 1.f);
        sgemm<0, 0><<<dim3(4, 128, 1), blk>>>(Agg, wq + l * HH, bq + l * CHID, nullptr, Qb,
                                              BN, CHID, CHID, 0, 0, 0, 1.f);
        // scores = softmax( Q @ K^T / 8 )   over 32 "heads" (contiguous reinterpret)
        sgemm<0, 1><<<dim3(16, 16, CB * CNH), blk>>>(Qb, Kb, nullptr, nullptr, sc,
                                                     CN, CN, CDH,
                                                     (long)CN * CDH, (long)CN * CDH,
                                                     (long)CN * CN, 0.125f);
        softmax1024<<<CB * CNH * CN, blk>>>(sc);
        // ctx = scores @ V
        sgemm<0, 0><<<dim3(1, 16, CB * CNH), blk>>>(sc, Vb, nullptr, nullptr, ctx,
                                                    CN, CDH, CN,
                                                    (long)CN * CN, (long)CN * CDH,
                                                    (long)CN * CDH, 1.f);
        // T = ctx @ wo + bo ;  H_new = LN(T + H)
        sgemm<0, 0><<<dim3(4, 128, 1), blk>>>(ctx, wo + l * HH, bo + l * CHID, nullptr, Tb,
                                              BN, CHID, CHID, 0, 0, 0, 1.f);
        ln_kernel<<<BN, blk>>>(Tb, cur, lng + l * CHID, lnb + l * CHID, nxt);

        // GRU speaker update (uses pre-update H)
        pagg_kernel<<<CB * CM, blk>>>(sadj, cur, Pagg);
        gru_kernel<<<CB * CM, blk>>>(P, Pagg,
                                     gwz + l * HH, guz + l * HH,
                                     gwr + l * HH, gur + l * HH,
                                     gw + l * HH,  gu + l * HH);
    }

    // logits = H @ out_w + out_b  (final H lives in g_H after 2 layers)
    sgemm<0, 0><<<dim3(1, 128, 1), blk>>>(H, outw, outb, nullptr, out,
                                          BN, CNC, CHID, 0, 0, 0, 1.f);
    // p_sim appended after logits
    psim_kernel<<<1, 64>>>(P, out + (long)BN * CNC, out_size - BN * CNC);
}

// round 2
// speedup vs baseline: 1.5994x; 1.5994x over previous
#include <cuda_runtime.h>
#include <math.h>
#include <stdint.h>

// ---------------- problem constants ----------------
constexpr int CB   = 8;      // batch
constexpr int CN   = 1024;   // nodes
constexpr int CM   = 8;      // speakers
constexpr int CDIN = 1024;
constexpr int CHID = 256;
constexpr int CL   = 2;
constexpr int CNC  = 7;
constexpr int CNH  = 4;
constexpr int CDH  = 64;
#define NEGF  (-9e15f)
#define ALPHAF 0.1f

// ---------------- scratch (static device memory; allocation-free) ----------------
__device__ float g_H   [CB*CN*CHID];
__device__ float g_Hn  [CB*CN*CHID];
__device__ float g_P   [CB*CM*CHID];
__device__ float g_Pagg[CB*CM*CHID];
__device__ float g_Pl1 [CB*CN*CHID];
__device__ float g_h   [CB*CN*CHID];
__device__ float g_Agg [CB*CN*CHID];
__device__ float g_Q   [CB*CN*CHID];
__device__ float g_K   [CB*CN*CHID];
__device__ float g_V   [CB*CN*CHID];
__device__ float g_ctx [CB*CN*CHID];
__device__ float g_T   [CB*CN*CHID];
__device__ float g_att [(long)CB*CN*CN];          // GAT attention  (33.5 MB)
__device__ float g_sc  [(long)CB*CNH*CN*CN];      // MHA scores     (134 MB)
__device__ float g_e1  [CB*CN];
__device__ float g_e2  [CB*CN];
__device__ float g_rsc [2];

// ---------------- tf32 helpers ----------------
__device__ __forceinline__ uint32_t f2tf(float f) {
    uint32_t u;
    asm("cvt.rna.tf32.f32 %0, %1;" : "=r"(u) : "f"(f));
    return u;
}
__device__ __forceinline__ void mma_tf32(float c[4], const uint32_t a[4], const uint32_t b[2]) {
    asm volatile(
        "mma.sync.aligned.m16n8k8.row.col.f32.tf32.tf32.f32 "
        "{%0,%1,%2,%3}, {%4,%5,%6,%7}, {%8,%9}, {%0,%1,%2,%3};\n"
        : "+f"(c[0]), "+f"(c[1]), "+f"(c[2]), "+f"(c[3])
        : "r"(a[0]), "r"(a[1]), "r"(a[2]), "r"(a[3]), "r"(b[0]), "r"(b[1]));
}

// ---------------- tf32 tensor-core GEMM ----------------
// C[M,N] = act( scale * A[M,K] @ B + bias ), B row-major [K,N] (TRANSB=0)
// or B row-major [N,K] used as B^T (TRANSB=1). Batched over blockIdx.z.
// Tiles: block 128x128, K-step 16. 8 warps: 2 (m) x 4 (n), warp tile 64x32.
// Requires K % 16 == 0, M % 4 == 0 rows loadable (M mult of 4 not needed: guarded).
template<int ACT, int TRANSB>
__global__ void __launch_bounds__(256) tgemm(
    const float* __restrict__ A, const float* __restrict__ Bm,
    const float* __restrict__ bias, float* __restrict__ C,
    int M, int N, int K, long sA, long sB, long sC, float scale)
{
    __shared__ uint32_t As[128 * 20];               // [m][k], stride 20
    __shared__ uint32_t Bs[2560];                   // TRANSB: [n][k] stride 20 ; else [k][n] stride 136

    int bz = blockIdx.z;
    A += (long)bz * sA;  Bm += (long)bz * sB;  C += (long)bz * sC;

    int tid  = threadIdx.x;
    int warp = tid >> 5, lane = tid & 31;
    int g = lane >> 2, tg = lane & 3;
    int mw = warp >> 2, nw = warp & 3;              // 2 x 4 warp grid
    int row0 = blockIdx.y * 128, col0 = blockIdx.x * 128;

    float acc[4][4][4] = {};

    for (int k0 = 0; k0 < K; k0 += 16) {
        // ---- load A tile 128x16 (2 float4 per thread) ----
        #pragma unroll
        for (int i = 0; i < 2; i++) {
            int f = tid * 2 + i;                    // 0..511
            int m = f >> 2, k4 = (f & 3) * 4;
            int gm = row0 + m;
            float4 v = make_float4(0.f, 0.f, 0.f, 0.f);
            if (gm < M) v = *(const float4*)(A + (long)gm * K + k0 + k4);
            uint32_t* d = &As[m * 20 + k4];
            d[0] = f2tf(v.x); d[1] = f2tf(v.y); d[2] = f2tf(v.z); d[3] = f2tf(v.w);
        }
        // ---- load B tile ----
        #pragma unroll
        for (int i = 0; i < 2; i++) {
            int f = tid * 2 + i;
            if (TRANSB) {                            // B [N,K]: tile [n=128][k=16]
                int n = f >> 2, k4 = (f & 3) * 4;
                int gn = col0 + n;
                float4 v = make_float4(0.f, 0.f, 0.f, 0.f);
                if (gn < N) v = *(const float4*)(Bm + (long)gn * K + k0 + k4);
                uint32_t* d = &Bs[n * 20 + k4];
                d[0] = f2tf(v.x); d[1] = f2tf(v.y); d[2] = f2tf(v.z); d[3] = f2tf(v.w);
            } else {                                 // B [K,N]: tile [k=16][n=128]
                int k = f >> 5, n4 = (f & 31) * 4;
                int gn = col0 + n4;
                float4 v = make_float4(0.f, 0.f, 0.f, 0.f);
                if (gn < N) v = *(const float4*)(Bm + (long)(k0 + k) * N + gn);
                uint32_t* d = &Bs[k * 136 + n4];
                d[0] = f2tf(v.x); d[1] = f2tf(v.y); d[2] = f2tf(v.z); d[3] = f2tf(v.w);
            }
        }
        __syncthreads();

        #pragma unroll
        for (int ks = 0; ks < 16; ks += 8) {
            uint32_t a[4][4], b[4][2];
            #pragma unroll
            for (int mi = 0; mi < 4; mi++) {
                int mr = mw * 64 + mi * 16;
                a[mi][0] = As[(mr + g)     * 20 + ks + tg];
                a[mi][1] = As[(mr + g + 8) * 20 + ks + tg];
                a[mi][2] = As[(mr + g)     * 20 + ks + tg + 4];
                a[mi][3] = As[(mr + g + 8) * 20 + ks + tg + 4];
            }
            #pragma unroll
            for (int ni = 0; ni < 4; ni++) {
                int nc = nw * 32 + ni * 8;
                if (TRANSB) {
                    b[ni][0] = Bs[(nc + g) * 20 + ks + tg];
                    b[ni][1] = Bs[(nc + g) * 20 + ks + tg + 4];
                } else {
                    b[ni][0] = Bs[(ks + tg)     * 136 + nc + g];
                    b[ni][1] = Bs[(ks + tg + 4) * 136 + nc + g];
                }
            }
            #pragma unroll
            for (int mi = 0; mi < 4; mi++)
                #pragma unroll
                for (int ni = 0; ni < 4; ni++)
                    mma_tf32(acc[mi][ni], a[mi], b[ni]);
        }
        __syncthreads();
    }

    // ---- epilogue ----
    #pragma unroll
    for (int mi = 0; mi < 4; mi++) {
        #pragma unroll
        for (int ni = 0; ni < 4; ni++) {
            int r0 = row0 + mw * 64 + mi * 16 + g;
            int c0 = col0 + nw * 32 + ni * 8 + tg * 2;
            #pragma unroll
            for (int rr = 0; rr < 2; rr++) {
                int r = r0 + rr * 8;
                if (r >= M) continue;
                #pragma unroll
                for (int cc = 0; cc < 2; cc++) {
                    int c = c0 + cc;
                    if (c >= N) continue;
                    float v = acc[mi][ni][rr * 2 + cc] * scale;
                    if (bias) v += bias[c];
                    if (ACT == 1) v = v > 0.f ? v : 0.f;
                    else if (ACT == 2) v = v > 0.f ? v : expm1f(v);
                    C[(long)r * N + c] = v;
                }
            }
        }
    }
}

// ---------------- fp32 tiled SGEMM (small cases: fc2, logits) ----------------
template<int ACT, int TRANSB>
__global__ void sgemm(const float* __restrict__ A, const float* __restrict__ Bm,
                      const float* __restrict__ bias, const float* __restrict__ Res,
                      float* __restrict__ C,
                      int M, int N, int K,
                      long sA, long sB, long sC, float scale)
{
    __shared__ float As[16][68];
    __shared__ float Bs[16][68];
    int bz = blockIdx.z;
    A  += (long)bz * sA;
    Bm += (long)bz * sB;
    C  += (long)bz * sC;

    int tx = threadIdx.x;
    int tr = tx >> 4, tc = tx & 15;
    int row0 = blockIdx.y * 64, col0 = blockIdx.x * 64;

    float acc[4][4] = {};
    for (int k0 = 0; k0 < K; k0 += 16) {
        #pragma unroll
        for (int i = 0; i < 4; i++) {
            int idx = tx * 4 + i;
            int m = idx >> 4, k = idx & 15;
            int gr = row0 + m;
            As[k][m] = (gr < M) ? A[(long)gr * K + k0 + k] : 0.f;
        }
        #pragma unroll
        for (int i = 0; i < 4; i++) {
            int idx = tx * 4 + i;
            if (TRANSB) {
                int n = idx >> 4, k = idx & 15;
                int gn = col0 + n;
                Bs[k][n] = (gn < N) ? Bm[(long)gn * K + k0 + k] : 0.f;
            } else {
                int k = idx >> 6, n = idx & 63;
                int gn = col0 + n;
                Bs[k][n] = (gn < N) ? Bm[(long)(k0 + k) * N + gn] : 0.f;
            }
        }
        __syncthreads();
        #pragma unroll
        for (int k = 0; k < 16; k++) {
            float a[4], b[4];
            #pragma unroll
            for (int i = 0; i < 4; i++) a[i] = As[k][tr * 4 + i];
            #pragma unroll
            for (int j = 0; j < 4; j++) b[j] = Bs[k][tc * 4 + j];
            #pragma unroll
            for (int i = 0; i < 4; i++)
                #pragma unroll
                for (int j = 0; j < 4; j++)
                    acc[i][j] = fmaf(a[i], b[j], acc[i][j]);
        }
        __syncthreads();
    }
    #pragma unroll
    for (int i = 0; i < 4; i++) {
        int gr = row0 + tr * 4 + i;
        if (gr >= M) continue;
        #pragma unroll
        for (int j = 0; j < 4; j++) {
            int gn = col0 + tc * 4 + j;
            if (gn >= N) continue;
            float v = acc[i][j] * scale;
            if (bias) v += bias[gn];
            if (Res)  v += Res[(long)bz * sC + (long)gr * N + gn];
            if (ACT == 1) v = v > 0.f ? v : 0.f;
            else if (ACT == 2) v = v > 0.f ? v : expm1f(v);
            C[(long)gr * N + gn] = v;
        }
    }
}

// ---------------- P_l_1[b,n,d] = sum_m s_adj[b,m,n] * P[b,m,d] ----------------
__global__ void pl1_kernel(const float* __restrict__ sadj, const float* __restrict__ P,
                           float* __restrict__ out)
{
    long idx = (long)blockIdx.x * 256 + threadIdx.x;
    int d = idx & (CHID - 1);
    int n = (idx >> 8) & (CN - 1);
    int b = (int)(idx >> 18);
    const float* sa = sadj + (long)b * CM * CN + n;
    const float* Pb = P + (long)b * CM * CHID + d;
    float acc = 0.f;
    #pragma unroll
    for (int m = 0; m < CM; m++) acc = fmaf(sa[m * CN], Pb[m * CHID], acc);
    out[idx] = acc;
}

// ---------------- P_agg[b,m,d] = sum_n s_adj[b,m,n] * H[b,n,d] ----------------
__global__ void pagg_kernel(const float* __restrict__ sadj, const float* __restrict__ H,
                            float* __restrict__ out)
{
    int bm = blockIdx.x;
    int b = bm >> 3;
    int d = threadIdx.x;
    const float* sa = sadj + (long)bm * CN;
    const float* Hb = H + (long)b * CN * CHID + d;
    float acc = 0.f;
    #pragma unroll 4
    for (int n = 0; n < CN; n++) acc = fmaf(sa[n], Hb[(long)n * CHID], acc);
    out[(long)bm * CHID + d] = acc;
}

// ---------------- e1/e2: per-row dots of h with a1, a2 ----------------
__global__ void dots_kernel(const float* __restrict__ h, const float* __restrict__ a1,
                            const float* __restrict__ a2,
                            float* __restrict__ e1, float* __restrict__ e2)
{
    __shared__ float s1[256], s2[256];
    int row = blockIdx.x, t = threadIdx.x;
    float v = h[(long)row * CHID + t];
    s1[t] = v * a1[t];
    s2[t] = v * a2[t];
    __syncthreads();
    for (int o = 128; o > 0; o >>= 1) {
        if (t < o) { s1[t] += s1[t + o]; s2[t] += s2[t + o]; }
        __syncthreads();
    }
    if (t == 0) { e1[row] = s1[0]; e2[row] = s2[0]; }
}

// ---------------- rel_sc[r] = dot(rel_emb[l][r], a3) ----------------
__global__ void relsc_kernel(const float* __restrict__ rel, const float* __restrict__ a3,
                             float* __restrict__ out)
{
    __shared__ float s[256];
    int r = blockIdx.x, t = threadIdx.x;
    s[t] = rel[r * CHID + t] * a3[t];
    __syncthreads();
    for (int o = 128; o > 0; o >>= 1) {
        if (t < o) s[t] += s[t + o];
        __syncthreads();
    }
    if (t == 0) out[r] = s[0];
}

// ---------------- GAT edge scores + masked softmax, one row per block ----------------
__global__ void gat_att_kernel(const float* __restrict__ e1, const float* __restrict__ e2,
                               const float* __restrict__ rsc,
                               const int* __restrict__ adj, const int* __restrict__ smask,
                               float* __restrict__ att)
{
    __shared__ float red[256];
    int bi = blockIdx.x;
    int b = bi >> 10;
    long base = (long)bi * CN;
    int t = threadIdx.x;
    float E1 = e1[bi];
    const float* e2b = e2 + b * CN;

    float vals[4];
    float mx = -3.4e38f;
    #pragma unroll
    for (int q = 0; q < 4; q++) {
        int j = t + q * 256;
        float e = E1 + e2b[j] + rsc[smask[base + j]];
        e = e >= 0.f ? e : ALPHAF * e;
        e = (adj[base + j] > 0) ? e : NEGF;
        vals[q] = e;
        mx = fmaxf(mx, e);
    }
    red[t] = mx; __syncthreads();
    for (int o = 128; o > 0; o >>= 1) {
        if (t < o) red[t] = fmaxf(red[t], red[t + o]);
        __syncthreads();
    }
    mx = red[0]; __syncthreads();
    float s = 0.f;
    #pragma unroll
    for (int q = 0; q < 4; q++) { vals[q] = expf(vals[q] - mx); s += vals[q]; }
    red[t] = s; __syncthreads();
    for (int o = 128; o > 0; o >>= 1) {
        if (t < o) red[t] += red[t + o];
        __syncthreads();
    }
    float inv = 1.f / red[0];
    #pragma unroll
    for (int q = 0; q < 4; q++) att[base + t + q * 256] = vals[q] * inv;
}

// ---------------- in-place row softmax over 1024 ----------------
__global__ void softmax1024(float* __restrict__ S)
{
    __shared__ float red[256];
    long base = (long)blockIdx.x * CN;
    int t = threadIdx.x;
    float vals[4];
    float mx = -3.4e38f;
    #pragma unroll
    for (int q = 0; q < 4; q++) { vals[q] = S[base + t + q * 256]; mx = fmaxf(mx, vals[q]); }
    red[t] = mx; __syncthreads();
    for (int o = 128; o > 0; o >>= 1) {
        if (t < o) red[t] = fmaxf(red[t], red[t + o]);
        __syncthreads();
    }
    mx = red[0]; __syncthreads();
    float s = 0.f;
    #pragma unroll
    for (int q = 0; q < 4; q++) { vals[q] = expf(vals[q] - mx); s += vals[q]; }
    red[t] = s; __syncthreads();
    for (int o = 128; o > 0; o >>= 1) {
        if (t < o) red[t] += red[t + o];
        __syncthreads();
    }
    float inv = 1.f / red[0];
    #pragma unroll
    for (int q = 0; q < 4; q++) S[base + t + q * 256] = vals[q] * inv;
}

// ---------------- LayerNorm( T + Hold ) * g + b ----------------
__global__ void ln_kernel(const float* __restrict__ T, const float* __restrict__ Hold,
                          const float* __restrict__ g, const float* __restrict__ bb,
                          float* __restrict__ out)
{
    __shared__ float red[256];
    int row = blockIdx.x, t = threadIdx.x;
    long off = (long)row * CHID + t;
    float v = T[off] + Hold[off];
    red[t] = v; __syncthreads();
    for (int o = 128; o > 0; o >>= 1) {
        if (t < o) red[t] += red[t + o];
        __syncthreads();
    }
    float mu = red[0] * (1.f / CHID);
    __syncthreads();
    float dv = v - mu;
    red[t] = dv * dv; __syncthreads();
    for (int o = 128; o > 0; o >>= 1) {
        if (t < o) red[t] += red[t + o];
        __syncthreads();
    }
    float var = red[0] * (1.f / CHID);
    out[off] = dv * rsqrtf(var + 1e-5f) * g[t] + bb[t];
}

// ---------------- GRU3d: in-place update of P (one row per block) ----------------
__global__ void gru_kernel(float* __restrict__ P, const float* __restrict__ Pagg,
                           const float* __restrict__ wz, const float* __restrict__ uz,
                           const float* __restrict__ wr, const float* __restrict__ ur,
                           const float* __restrict__ w,  const float* __restrict__ u)
{
    __shared__ float sp[CHID], sq[CHID];
    int r = blockIdx.x;
    int c = threadIdx.x;
    sp[c] = P[(long)r * CHID + c];
    sq[c] = Pagg[(long)r * CHID + c];
    __syncthreads();
    float az = 0, bz = 0, ar = 0, br = 0, aw = 0, bw = 0;
    for (int k = 0; k < CHID; k++) {
        float pk = sp[k], qk = sq[k];
        az = fmaf(pk, wz[k * CHID + c], az); bz = fmaf(qk, uz[k * CHID + c], bz);
        ar = fmaf(pk, wr[k * CHID + c], ar); br = fmaf(qk, ur[k * CHID + c], br);
        aw = fmaf(pk, w [k * CHID + c], aw); bw = fmaf(qk, u [k * CHID + c], bw);
    }
    float z  = 1.f / (1.f + expf(-(az + bz)));
    float rr = 1.f / (1.f + expf(-(ar + br)));
    float hh = tanhf(aw + rr * bw);
    P[(long)r * CHID + c] = (1.f - z) * sp[c] + z * hh;
}

// ---------------- p_sim ----------------
__global__ void psim_kernel(const float* __restrict__ P, float* __restrict__ outp, int tail)
{
    __shared__ float red[64];
    int t = threadIdx.x;
    int b = t >> 3, m = t & 7;
    const float* Pb = P + (long)b * CM * CHID;
    float s = 0.f;
    for (int k2 = 0; k2 < CM; k2++) {
        if (k2 == m) continue;
        float d = 0.f;
        for (int dd = 0; dd < CHID; dd++)
            d = fmaf(Pb[m * CHID + dd], Pb[k2 * CHID + dd], d);
        s += d;
    }
    red[t] = s; __syncthreads();
    if ((t & 7) < 4) red[t] += red[t + 4]; __syncthreads();
    if ((t & 7) < 2) red[t] += red[t + 2]; __syncthreads();
    if ((t & 7) < 1) red[t] += red[t + 1]; __syncthreads();
    if (tail >= CB) {
        if (t < CB) outp[t] = red[t * 8] / (float)(CM * CM);
    } else {
        if (t == 0) {
            float tot = 0.f;
            for (int b2 = 0; b2 < CB; b2++) tot += red[b2 * 8];
            outp[0] = tot / (float)(CB * CM * CM);
        }
    }
}

// ---------------- host orchestration ----------------
extern "C" void kernel_launch(void* const* d_in, const int* in_sizes, int n_in,
                              void* d_out, int out_size)
{
    const float* x     = (const float*)d_in[0];
    const int*   adj   = (const int*)  d_in[1];
    const int*   smask = (const int*)  d_in[2];
    const float* sf    = (const float*)d_in[3];
    const float* sadj  = (const float*)d_in[4];
    const float* fc1w  = (const float*)d_in[6];
    const float* fc1b  = (const float*)d_in[7];
    const float* fc2w  = (const float*)d_in[8];
    const float* fc2b  = (const float*)d_in[9];
    const float* gatW  = (const float*)d_in[10];
    const float* gata  = (const float*)d_in[11];
    const float* rel   = (const float*)d_in[12];
    const float* gwz   = (const float*)d_in[13];
    const float* guz   = (const float*)d_in[14];
    const float* gwr   = (const float*)d_in[15];
    const float* gur   = (const float*)d_in[16];
    const float* gw    = (const float*)d_in[17];
    const float* gu    = (const float*)d_in[18];
    const float* wv    = (const float*)d_in[19];
    const float* bv    = (const float*)d_in[20];
    const float* wk    = (const float*)d_in[21];
    const float* bk    = (const float*)d_in[22];
    const float* wq    = (const float*)d_in[23];
    const float* bq    = (const float*)d_in[24];
    const float* wo    = (const float*)d_in[25];
    const float* bo    = (const float*)d_in[26];
    const float* lng   = (const float*)d_in[27];
    const float* lnb   = (const float*)d_in[28];
    const float* outw  = (const float*)d_in[29];
    const float* outb  = (const float*)d_in[30];
    float* out = (float*)d_out;

    float *H, *Hn, *P, *Pagg, *Pl1, *hb, *Agg, *Qb, *Kb, *Vb, *ctx, *Tb, *att, *sc, *e1, *e2, *rsc;
    cudaGetSymbolAddress((void**)&H,    g_H);
    cudaGetSymbolAddress((void**)&Hn,   g_Hn);
    cudaGetSymbolAddress((void**)&P,    g_P);
    cudaGetSymbolAddress((void**)&Pagg, g_Pagg);
    cudaGetSymbolAddress((void**)&Pl1,  g_Pl1);
    cudaGetSymbolAddress((void**)&hb,   g_h);
    cudaGetSymbolAddress((void**)&Agg,  g_Agg);
    cudaGetSymbolAddress((void**)&Qb,   g_Q);
    cudaGetSymbolAddress((void**)&Kb,   g_K);
    cudaGetSymbolAddress((void**)&Vb,   g_V);
    cudaGetSymbolAddress((void**)&ctx,  g_ctx);
    cudaGetSymbolAddress((void**)&Tb,   g_T);
    cudaGetSymbolAddress((void**)&att,  g_att);
    cudaGetSymbolAddress((void**)&sc,   g_sc);
    cudaGetSymbolAddress((void**)&e1,   g_e1);
    cudaGetSymbolAddress((void**)&e2,   g_e2);
    cudaGetSymbolAddress((void**)&rsc,  g_rsc);

    dim3 blk(256);
    const int BN = CB * CN;                          // 8192
    const long HH = (long)CHID * CHID;               // 65536

    // H = relu(x @ fc1_w + b)  [tensor core]
    tgemm<1, 0><<<dim3(2, 64, 1), blk>>>(x, fc1w, fc1b, H, BN, CHID, CDIN, 0, 0, 0, 1.f);
    // P = relu(s_feature @ fc2_w + b)  [small, fp32]
    sgemm<1, 0><<<dim3(4, 1, 1), blk>>>(sf, fc2w, fc2b, nullptr, P, CB * CM, CHID, CDIN, 0, 0, 0, 1.f);

    for (int l = 0; l < CL; l++) {
        float* cur = l ? Hn : H;
        float* nxt = l ? H : Hn;

        // P_l_1 = s_adj^T @ P
        pl1_kernel<<<BN * CHID / 256, blk>>>(sadj, P, Pl1);

        // h = H @ gat_W[l]
        tgemm<0, 0><<<dim3(2, 64, 1), blk>>>(cur, gatW + l * HH, nullptr, hb,
                                             BN, CHID, CHID, 0, 0, 0, 1.f);
        // edge-score ingredients
        dots_kernel<<<BN, blk>>>(hb, gata + l * 3 * CHID, gata + l * 3 * CHID + CHID, e1, e2);
        relsc_kernel<<<2, blk>>>(rel + l * 2 * CHID, gata + l * 3 * CHID + 2 * CHID, rsc);
        // masked softmax rows of att
        gat_att_kernel<<<BN, blk>>>(e1, e2, rsc, adj, smask, att);
        // Agg = elu(att @ h)   (batched over b)
        tgemm<2, 0><<<dim3(2, 8, CB), blk>>>(att, hb, nullptr, Agg,
                                             CN, CHID, CN,
                                             (long)CN * CN, (long)CN * CHID, (long)CN * CHID, 1.f);
        // projections
        tgemm<0, 0><<<dim3(2, 64, 1), blk>>>(cur, wv + l * HH, bv + l * CHID, Vb,
                                             BN, CHID, CHID, 0, 0, 0, 1.f);
        tgemm<0, 0><<<dim3(2, 64, 1), blk>>>(Pl1, wk + l * HH, bk + l * CHID, Kb,
                                             BN, CHID, CHID, 0, 0, 0, 1.f);
        tgemm<0, 0><<<dim3(2, 64, 1), blk>>>(Agg, wq + l * HH, bq + l * CHID, Qb,
                                             BN, CHID, CHID, 0, 0, 0, 1.f);
        // scores = softmax( Q @ K^T / 8 )   over 32 "heads" (contiguous reinterpret)
        tgemm<0, 1><<<dim3(8, 8, CB * CNH), blk>>>(Qb, Kb, nullptr, sc,
                                                   CN, CN, CDH,
                                                   (long)CN * CDH, (long)CN * CDH,
                                                   (long)CN * CN, 0.125f);
        softmax1024<<<CB * CNH * CN, blk>>>(sc);
        // ctx = scores @ V
        tgemm<0, 0><<<dim3(1, 8, CB * CNH), blk>>>(sc, Vb, nullptr, ctx,
                                                   CN, CDH, CN,
                                                   (long)CN * CN, (long)CN * CDH,
                                                   (long)CN * CDH, 1.f);
        // T = ctx @ wo + bo ;  H_new = LN(T + H)
        tgemm<0, 0><<<dim3(2, 64, 1), blk>>>(ctx, wo + l * HH, bo + l * CHID, Tb,
                                             BN, CHID, CHID, 0, 0, 0, 1.f);
        ln_kernel<<<BN, blk>>>(Tb, cur, lng + l * CHID, lnb + l * CHID, nxt);

        // GRU speaker update (uses pre-update H)
        pagg_kernel<<<CB * CM, blk>>>(sadj, cur, Pagg);
        gru_kernel<<<CB * CM, blk>>>(P, Pagg,
                                     gwz + l * HH, guz + l * HH,
                                     gwr + l * HH, gur + l * HH,
                                     gw + l * HH,  gu + l * HH);
    }

    // logits = H @ out_w + out_b  (final H lives in g_H after 2 layers)
    sgemm<0, 0><<<dim3(1, 128, 1), blk>>>(H, outw, outb, nullptr, out,
                                          BN, CNC, CHID, 0, 0, 0, 1.f);
    // p_sim appended after logits
    psim_kernel<<<1, 64>>>(P, out + (long)BN * CNC, out_size - BN * CNC);
}

// round 3
// speedup vs baseline: 2.0173x; 1.2613x over previous
#include <cuda_runtime.h>
#include <math.h>
#include <stdint.h>

// ---------------- problem constants ----------------
constexpr int CB   = 8;      // batch
constexpr int CN   = 1024;   // nodes
constexpr int CM   = 8;      // speakers
constexpr int CDIN = 1024;
constexpr int CHID = 256;
constexpr int CL   = 2;
constexpr int CNC  = 7;
constexpr int CNH  = 4;
constexpr int CDH  = 64;
#define NEGF  (-9e15f)
#define ALPHAF 0.1f

// ---------------- scratch (static device memory; allocation-free) ----------------
__device__ float g_H   [CB*CN*CHID];
__device__ float g_Hn  [CB*CN*CHID];
__device__ float g_P   [CB*CM*CHID];
__device__ float g_Pagg[CB*CM*CHID];
__device__ float g_Pl1 [CB*CN*CHID];
__device__ float g_h   [CB*CN*CHID];
__device__ float g_Agg [CB*CN*CHID];
__device__ float g_Q   [CB*CN*CHID];
__device__ float g_K   [CB*CN*CHID];
__device__ float g_V   [CB*CN*CHID];
__device__ float g_ctx [CB*CN*CHID];
__device__ float g_T   [CB*CN*CHID];
__device__ float g_att [(long)CB*CN*CN];          // GAT attention  (33.5 MB)
__device__ float g_sc  [(long)CB*CNH*CN*CN];      // MHA scores     (134 MB)
__device__ float g_e1  [CB*CN];
__device__ float g_e2  [CB*CN];
__device__ float g_rsc [2];

// ---------------- tf32 helpers ----------------
__device__ __forceinline__ uint32_t f2tf(float f) {
    uint32_t u;
    asm("cvt.rna.tf32.f32 %0, %1;" : "=r"(u) : "f"(f));
    return u;
}
__device__ __forceinline__ void mma_tf32(float c[4], const uint32_t a[4], const uint32_t b[2]) {
    asm volatile(
        "mma.sync.aligned.m16n8k8.row.col.f32.tf32.tf32.f32 "
        "{%0,%1,%2,%3}, {%4,%5,%6,%7}, {%8,%9}, {%0,%1,%2,%3};\n"
        : "+f"(c[0]), "+f"(c[1]), "+f"(c[2]), "+f"(c[3])
        : "r"(a[0]), "r"(a[1]), "r"(a[2]), "r"(a[3]), "r"(b[0]), "r"(b[1]));
}
__device__ __forceinline__ void cpasync16(uint32_t saddr, const void* gptr) {
    asm volatile("cp.async.cg.shared.global [%0], [%1], 16;\n" :: "r"(saddr), "l"(gptr));
}
__device__ __forceinline__ void cpcommit() { asm volatile("cp.async.commit_group;\n"); }
__device__ __forceinline__ void cpwait0()  { asm volatile("cp.async.wait_group 0;\n"); }

// ---------------- pipelined tf32 tensor-core GEMM ----------------
// C[M,N] = act( scale * A[M,K] @ B + bias ), TRANSB=0: B row-major [K,N];
// TRANSB=1: B row-major [N,K] used as B^T. Batched over blockIdx.z.
// REQUIRES: M % 128 == 0, N % TN == 0, K % 32 == 0 (no guards).
// Block tile 128 x TN, K-step 32, 2-stage cp.async pipeline, 8 warps.
template<int ACT, int TRANSB, int TN>
__global__ void __launch_bounds__(256) tgemm(
    const float* __restrict__ A, const float* __restrict__ Bm,
    const float* __restrict__ bias, float* __restrict__ C,
    int M, int N, int K, long sA, long sB, long sC, float scale)
{
    constexpr int TM = 128;
    constexpr int KS = 32;
    constexpr int WC = (TN == 128) ? 4 : 2;      // warps along n
    constexpr int MI = (TN == 128) ? 4 : 2;      // 16-row frags per warp
    constexpr int NI = 4;                        // 8-col frags per warp
    constexpr int strA = 36;                     // words, padded (bank-clean, 16B aligned)
    constexpr int strB0 = TN + 4;                // 132 or 68
    constexpr int AW = TM * strA;                // words per A stage
    constexpr int BW = TRANSB ? (TN * strA) : (KS * strB0);

    extern __shared__ float smem[];
    float* As = smem;                  // [2][AW]
    float* Bs = smem + 2 * AW;         // [2][BW]
    uint32_t As_b = (uint32_t)__cvta_generic_to_shared(As);
    uint32_t Bs_b = (uint32_t)__cvta_generic_to_shared(Bs);

    int bz = blockIdx.z;
    A += (long)bz * sA;  Bm += (long)bz * sB;  C += (long)bz * sC;

    int tid  = threadIdx.x;
    int warp = tid >> 5, lane = tid & 31;
    int g = lane >> 2, tg = lane & 3;
    int mw = warp / WC, nw = warp % WC;
    int row0 = blockIdx.y * TM, col0 = blockIdx.x * TN;

    const float* Ag = A + (long)row0 * K;
    const float* Bg = TRANSB ? (Bm + (long)col0 * K) : (Bm + col0);

    float acc[MI][NI][4];
    #pragma unroll
    for (int mi = 0; mi < MI; mi++)
        #pragma unroll
        for (int ni = 0; ni < NI; ni++)
            #pragma unroll
            for (int q = 0; q < 4; q++) acc[mi][ni][q] = 0.f;

    int nk = K / KS;

    auto load_stage = [&](int kt, int s) {
        int k0 = kt * KS;
        // A tile: 128 x 32 -> 1024 float4, 4 per thread
        #pragma unroll
        for (int i = 0; i < 4; i++) {
            int f = tid + i * 256;
            int m = f >> 3, k4 = (f & 7) * 4;
            cpasync16(As_b + (uint32_t)(((s * TM + m) * strA + k4) * 4),
                      Ag + (long)m * K + k0 + k4);
        }
        if (TRANSB) {   // B [N,K] tile: TN x 32
            #pragma unroll
            for (int i = 0; i < TN / 32; i++) {
                int f = tid + i * 256;
                int n = f >> 3, k4 = (f & 7) * 4;
                cpasync16(Bs_b + (uint32_t)(((s * TN + n) * strA + k4) * 4),
                          Bg + (long)n * K + k0 + k4);
            }
        } else {        // B [K,N] tile: 32 x TN
            #pragma unroll
            for (int i = 0; i < TN / 32; i++) {
                int f = tid + i * 256;
                int k = f / (TN / 4), n4 = (f % (TN / 4)) * 4;
                cpasync16(Bs_b + (uint32_t)(((s * KS + k) * strB0 + n4) * 4),
                          Bg + (long)(k0 + k) * N + n4);
            }
        }
        cpcommit();
    };

    load_stage(0, 0);

    for (int kt = 0; kt < nk; kt++) {
        cpwait0();
        __syncthreads();
        int s = kt & 1;
        if (kt + 1 < nk) load_stage(kt + 1, s ^ 1);

        const float* Asb = As + s * AW;
        const float* Bsb = Bs + s * BW;
        #pragma unroll
        for (int ks = 0; ks < KS; ks += 8) {
            uint32_t a[MI][4], b[NI][2];
            #pragma unroll
            for (int mi = 0; mi < MI; mi++) {
                int mr = mw * (MI * 16) + mi * 16;
                a[mi][0] = f2tf(Asb[(mr + g)     * strA + ks + tg]);
                a[mi][1] = f2tf(Asb[(mr + g + 8) * strA + ks + tg]);
                a[mi][2] = f2tf(Asb[(mr + g)     * strA + ks + tg + 4]);
                a[mi][3] = f2tf(Asb[(mr + g + 8) * strA + ks + tg + 4]);
            }
            #pragma unroll
            for (int ni = 0; ni < NI; ni++) {
                int nc = nw * (NI * 8) + ni * 8;
                if (TRANSB) {
                    b[ni][0] = f2tf(Bsb[(nc + g) * strA + ks + tg]);
                    b[ni][1] = f2tf(Bsb[(nc + g) * strA + ks + tg + 4]);
                } else {
                    b[ni][0] = f2tf(Bsb[(ks + tg)     * strB0 + nc + g]);
                    b[ni][1] = f2tf(Bsb[(ks + tg + 4) * strB0 + nc + g]);
                }
            }
            #pragma unroll
            for (int mi = 0; mi < MI; mi++)
                #pragma unroll
                for (int ni = 0; ni < NI; ni++)
                    mma_tf32(acc[mi][ni], a[mi], b[ni]);
        }
        __syncthreads();
    }

    // ---- epilogue (no bounds checks; float2 stores) ----
    #pragma unroll
    for (int mi = 0; mi < MI; mi++) {
        #pragma unroll
        for (int ni = 0; ni < NI; ni++) {
            int r = row0 + mw * (MI * 16) + mi * 16 + g;
            int c = col0 + nw * (NI * 8) + ni * 8 + tg * 2;
            float b0 = bias ? bias[c] : 0.f;
            float b1 = bias ? bias[c + 1] : 0.f;
            #pragma unroll
            for (int rr = 0; rr < 2; rr++) {
                float v0 = acc[mi][ni][rr * 2 + 0] * scale + b0;
                float v1 = acc[mi][ni][rr * 2 + 1] * scale + b1;
                if (ACT == 1) { v0 = fmaxf(v0, 0.f); v1 = fmaxf(v1, 0.f); }
                else if (ACT == 2) {
                    v0 = v0 > 0.f ? v0 : expm1f(v0);
                    v1 = v1 > 0.f ? v1 : expm1f(v1);
                }
                *(float2*)(C + (long)(r + rr * 8) * N + c) = make_float2(v0, v1);
            }
        }
    }
}

// smem byte sizes per instantiation
constexpr int SM_T0_128 = (2 * 128 * 36 + 2 * 32 * 132) * 4;   // 70656
constexpr int SM_T1_128 = (2 * 128 * 36 + 2 * 128 * 36) * 4;   // 73728
constexpr int SM_T0_64  = (2 * 128 * 36 + 2 * 32 * 68) * 4;    // 54272

// ---------------- fp32 tiled SGEMM (small/ragged cases: fc2, logits) ----------------
template<int ACT, int TRANSB>
__global__ void sgemm(const float* __restrict__ A, const float* __restrict__ Bm,
                      const float* __restrict__ bias, const float* __restrict__ Res,
                      float* __restrict__ C,
                      int M, int N, int K,
                      long sA, long sB, long sC, float scale)
{
    __shared__ float As[16][68];
    __shared__ float Bs[16][68];
    int bz = blockIdx.z;
    A  += (long)bz * sA;
    Bm += (long)bz * sB;
    C  += (long)bz * sC;

    int tx = threadIdx.x;
    int tr = tx >> 4, tc = tx & 15;
    int row0 = blockIdx.y * 64, col0 = blockIdx.x * 64;

    float acc[4][4] = {};
    for (int k0 = 0; k0 < K; k0 += 16) {
        #pragma unroll
        for (int i = 0; i < 4; i++) {
            int idx = tx * 4 + i;
            int m = idx >> 4, k = idx & 15;
            int gr = row0 + m;
            As[k][m] = (gr < M) ? A[(long)gr * K + k0 + k] : 0.f;
        }
        #pragma unroll
        for (int i = 0; i < 4; i++) {
            int idx = tx * 4 + i;
            if (TRANSB) {
                int n = idx >> 4, k = idx & 15;
                int gn = col0 + n;
                Bs[k][n] = (gn < N) ? Bm[(long)gn * K + k0 + k] : 0.f;
            } else {
                int k = idx >> 6, n = idx & 63;
                int gn = col0 + n;
                Bs[k][n] = (gn < N) ? Bm[(long)(k0 + k) * N + gn] : 0.f;
            }
        }
        __syncthreads();
        #pragma unroll
        for (int k = 0; k < 16; k++) {
            float a[4], b[4];
            #pragma unroll
            for (int i = 0; i < 4; i++) a[i] = As[k][tr * 4 + i];
            #pragma unroll
            for (int j = 0; j < 4; j++) b[j] = Bs[k][tc * 4 + j];
            #pragma unroll
            for (int i = 0; i < 4; i++)
                #pragma unroll
                for (int j = 0; j < 4; j++)
                    acc[i][j] = fmaf(a[i], b[j], acc[i][j]);
        }
        __syncthreads();
    }
    #pragma unroll
    for (int i = 0; i < 4; i++) {
        int gr = row0 + tr * 4 + i;
        if (gr >= M) continue;
        #pragma unroll
        for (int j = 0; j < 4; j++) {
            int gn = col0 + tc * 4 + j;
            if (gn >= N) continue;
            float v = acc[i][j] * scale;
            if (bias) v += bias[gn];
            if (Res)  v += Res[(long)bz * sC + (long)gr * N + gn];
            if (ACT == 1) v = v > 0.f ? v : 0.f;
            else if (ACT == 2) v = v > 0.f ? v : expm1f(v);
            C[(long)gr * N + gn] = v;
        }
    }
}

// ---------------- P_l_1[b,n,d] = sum_m s_adj[b,m,n] * P[b,m,d] ----------------
__global__ void pl1_kernel(const float* __restrict__ sadj, const float* __restrict__ P,
                           float* __restrict__ out)
{
    long idx = (long)blockIdx.x * 256 + threadIdx.x;
    int d = idx & (CHID - 1);
    int n = (idx >> 8) & (CN - 1);
    int b = (int)(idx >> 18);
    const float* sa = sadj + (long)b * CM * CN + n;
    const float* Pb = P + (long)b * CM * CHID + d;
    float acc = 0.f;
    #pragma unroll
    for (int m = 0; m < CM; m++) acc = fmaf(sa[m * CN], Pb[m * CHID], acc);
    out[idx] = acc;
}

// ---------------- P_agg[b,m,d] = sum_n s_adj[b,m,n] * H[b,n,d] ----------------
__global__ void pagg_kernel(const float* __restrict__ sadj, const float* __restrict__ H,
                            float* __restrict__ out)
{
    int bm = blockIdx.x;
    int b = bm >> 3;
    int d = threadIdx.x;
    const float* sa = sadj + (long)bm * CN;
    const float* Hb = H + (long)b * CN * CHID + d;
    float acc = 0.f;
    #pragma unroll 4
    for (int n = 0; n < CN; n++) acc = fmaf(sa[n], Hb[(long)n * CHID], acc);
    out[(long)bm * CHID + d] = acc;
}

// ---------------- e1/e2: per-row dots of h with a1, a2 ----------------
__global__ void dots_kernel(const float* __restrict__ h, const float* __restrict__ a1,
                            const float* __restrict__ a2,
                            float* __restrict__ e1, float* __restrict__ e2)
{
    __shared__ float s1[256], s2[256];
    int row = blockIdx.x, t = threadIdx.x;
    float v = h[(long)row * CHID + t];
    s1[t] = v * a1[t];
    s2[t] = v * a2[t];
    __syncthreads();
    for (int o = 128; o > 0; o >>= 1) {
        if (t < o) { s1[t] += s1[t + o]; s2[t] += s2[t + o]; }
        __syncthreads();
    }
    if (t == 0) { e1[row] = s1[0]; e2[row] = s2[0]; }
}

// ---------------- rel_sc[r] = dot(rel_emb[l][r], a3) ----------------
__global__ void relsc_kernel(const float* __restrict__ rel, const float* __restrict__ a3,
                             float* __restrict__ out)
{
    __shared__ float s[256];
    int r = blockIdx.x, t = threadIdx.x;
    s[t] = rel[r * CHID + t] * a3[t];
    __syncthreads();
    for (int o = 128; o > 0; o >>= 1) {
        if (t < o) s[t] += s[t + o];
        __syncthreads();
    }
    if (t == 0) out[r] = s[0];
}

// ---------------- GAT edge scores + masked softmax, one row per block ----------------
__global__ void gat_att_kernel(const float* __restrict__ e1, const float* __restrict__ e2,
                               const float* __restrict__ rsc,
                               const int* __restrict__ adj, const int* __restrict__ smask,
                               float* __restrict__ att)
{
    __shared__ float red[256];
    int bi = blockIdx.x;
    int b = bi >> 10;
    long base = (long)bi * CN;
    int t = threadIdx.x;
    float E1 = e1[bi];
    const float* e2b = e2 + b * CN;

    float vals[4];
    float mx = -3.4e38f;
    #pragma unroll
    for (int q = 0; q < 4; q++) {
        int j = t + q * 256;
        float e = E1 + e2b[j] + rsc[smask[base + j]];
        e = e >= 0.f ? e : ALPHAF * e;
        e = (adj[base + j] > 0) ? e : NEGF;
        vals[q] = e;
        mx = fmaxf(mx, e);
    }
    red[t] = mx; __syncthreads();
    for (int o = 128; o > 0; o >>= 1) {
        if (t < o) red[t] = fmaxf(red[t], red[t + o]);
        __syncthreads();
    }
    mx = red[0]; __syncthreads();
    float s = 0.f;
    #pragma unroll
    for (int q = 0; q < 4; q++) { vals[q] = expf(vals[q] - mx); s += vals[q]; }
    red[t] = s; __syncthreads();
    for (int o = 128; o > 0; o >>= 1) {
        if (t < o) red[t] += red[t + o];
        __syncthreads();
    }
    float inv = 1.f / red[0];
    #pragma unroll
    for (int q = 0; q < 4; q++) att[base + t + q * 256] = vals[q] * inv;
}

// ---------------- in-place row softmax over 1024 ----------------
__global__ void softmax1024(float* __restrict__ S)
{
    __shared__ float red[256];
    long base = (long)blockIdx.x * CN;
    int t = threadIdx.x;
    float vals[4];
    float mx = -3.4e38f;
    #pragma unroll
    for (int q = 0; q < 4; q++) { vals[q] = S[base + t + q * 256]; mx = fmaxf(mx, vals[q]); }
    red[t] = mx; __syncthreads();
    for (int o = 128; o > 0; o >>= 1) {
        if (t < o) red[t] = fmaxf(red[t], red[t + o]);
        __syncthreads();
    }
    mx = red[0]; __syncthreads();
    float s = 0.f;
    #pragma unroll
    for (int q = 0; q < 4; q++) { vals[q] = expf(vals[q] - mx); s += vals[q]; }
    red[t] = s; __syncthreads();
    for (int o = 128; o > 0; o >>= 1) {
        if (t < o) red[t] += red[t + o];
        __syncthreads();
    }
    float inv = 1.f / red[0];
    #pragma unroll
    for (int q = 0; q < 4; q++) S[base + t + q * 256] = vals[q] * inv;
}

// ---------------- LayerNorm( T + Hold ) * g + b ----------------
__global__ void ln_kernel(const float* __restrict__ T, const float* __restrict__ Hold,
                          const float* __restrict__ g, const float* __restrict__ bb,
                          float* __restrict__ out)
{
    __shared__ float red[256];
    int row = blockIdx.x, t = threadIdx.x;
    long off = (long)row * CHID + t;
    float v = T[off] + Hold[off];
    red[t] = v; __syncthreads();
    for (int o = 128; o > 0; o >>= 1) {
        if (t < o) red[t] += red[t + o];
        __syncthreads();
    }
    float mu = red[0] * (1.f / CHID);
    __syncthreads();
    float dv = v - mu;
    red[t] = dv * dv; __syncthreads();
    for (int o = 128; o > 0; o >>= 1) {
        if (t < o) red[t] += red[t + o];
        __syncthreads();
    }
    float var = red[0] * (1.f / CHID);
    out[off] = dv * rsqrtf(var + 1e-5f) * g[t] + bb[t];
}

// ---------------- GRU3d: in-place update of P (one row per block) ----------------
__global__ void gru_kernel(float* __restrict__ P, const float* __restrict__ Pagg,
                           const float* __restrict__ wz, const float* __restrict__ uz,
                           const float* __restrict__ wr, const float* __restrict__ ur,
                           const float* __restrict__ w,  const float* __restrict__ u)
{
    __shared__ float sp[CHID], sq[CHID];
    int r = blockIdx.x;
    int c = threadIdx.x;
    sp[c] = P[(long)r * CHID + c];
    sq[c] = Pagg[(long)r * CHID + c];
    __syncthreads();
    float az = 0, bz = 0, ar = 0, br = 0, aw = 0, bw = 0;
    for (int k = 0; k < CHID; k++) {
        float pk = sp[k], qk = sq[k];
        az = fmaf(pk, wz[k * CHID + c], az); bz = fmaf(qk, uz[k * CHID + c], bz);
        ar = fmaf(pk, wr[k * CHID + c], ar); br = fmaf(qk, ur[k * CHID + c], br);
        aw = fmaf(pk, w [k * CHID + c], aw); bw = fmaf(qk, u [k * CHID + c], bw);
    }
    float z  = 1.f / (1.f + expf(-(az + bz)));
    float rr = 1.f / (1.f + expf(-(ar + br)));
    float hh = tanhf(aw + rr * bw);
    P[(long)r * CHID + c] = (1.f - z) * sp[c] + z * hh;
}

// ---------------- p_sim ----------------
__global__ void psim_kernel(const float* __restrict__ P, float* __restrict__ outp, int tail)
{
    __shared__ float red[64];
    int t = threadIdx.x;
    int b = t >> 3, m = t & 7;
    const float* Pb = P + (long)b * CM * CHID;
    float s = 0.f;
    for (int k2 = 0; k2 < CM; k2++) {
        if (k2 == m) continue;
        float d = 0.f;
        for (int dd = 0; dd < CHID; dd++)
            d = fmaf(Pb[m * CHID + dd], Pb[k2 * CHID + dd], d);
        s += d;
    }
    red[t] = s; __syncthreads();
    if ((t & 7) < 4) red[t] += red[t + 4]; __syncthreads();
    if ((t & 7) < 2) red[t] += red[t + 2]; __syncthreads();
    if ((t & 7) < 1) red[t] += red[t + 1]; __syncthreads();
    if (tail >= CB) {
        if (t < CB) outp[t] = red[t * 8] / (float)(CM * CM);
    } else {
        if (t == 0) {
            float tot = 0.f;
            for (int b2 = 0; b2 < CB; b2++) tot += red[b2 * 8];
            outp[0] = tot / (float)(CB * CM * CM);
        }
    }
}

// ---------------- host orchestration ----------------
extern "C" void kernel_launch(void* const* d_in, const int* in_sizes, int n_in,
                              void* d_out, int out_size)
{
    const float* x     = (const float*)d_in[0];
    const int*   adj   = (const int*)  d_in[1];
    const int*   smask = (const int*)  d_in[2];
    const float* sf    = (const float*)d_in[3];
    const float* sadj  = (const float*)d_in[4];
    const float* fc1w  = (const float*)d_in[6];
    const float* fc1b  = (const float*)d_in[7];
    const float* fc2w  = (const float*)d_in[8];
    const float* fc2b  = (const float*)d_in[9];
    const float* gatW  = (const float*)d_in[10];
    const float* gata  = (const float*)d_in[11];
    const float* rel   = (const float*)d_in[12];
    const float* gwz   = (const float*)d_in[13];
    const float* guz   = (const float*)d_in[14];
    const float* gwr   = (const float*)d_in[15];
    const float* gur   = (const float*)d_in[16];
    const float* gw    = (const float*)d_in[17];
    const float* gu    = (const float*)d_in[18];
    const float* wv    = (const float*)d_in[19];
    const float* bv    = (const float*)d_in[20];
    const float* wk    = (const float*)d_in[21];
    const float* bk    = (const float*)d_in[22];
    const float* wq    = (const float*)d_in[23];
    const float* bq    = (const float*)d_in[24];
    const float* wo    = (const float*)d_in[25];
    const float* bo    = (const float*)d_in[26];
    const float* lng   = (const float*)d_in[27];
    const float* lnb   = (const float*)d_in[28];
    const float* outw  = (const float*)d_in[29];
    const float* outb  = (const float*)d_in[30];
    float* out = (float*)d_out;

    float *H, *Hn, *P, *Pagg, *Pl1, *hb, *Agg, *Qb, *Kb, *Vb, *ctx, *Tb, *att, *sc, *e1, *e2, *rsc;
    cudaGetSymbolAddress((void**)&H,    g_H);
    cudaGetSymbolAddress((void**)&Hn,   g_Hn);
    cudaGetSymbolAddress((void**)&P,    g_P);
    cudaGetSymbolAddress((void**)&Pagg, g_Pagg);
    cudaGetSymbolAddress((void**)&Pl1,  g_Pl1);
    cudaGetSymbolAddress((void**)&hb,   g_h);
    cudaGetSymbolAddress((void**)&Agg,  g_Agg);
    cudaGetSymbolAddress((void**)&Qb,   g_Q);
    cudaGetSymbolAddress((void**)&Kb,   g_K);
    cudaGetSymbolAddress((void**)&Vb,   g_V);
    cudaGetSymbolAddress((void**)&ctx,  g_ctx);
    cudaGetSymbolAddress((void**)&Tb,   g_T);
    cudaGetSymbolAddress((void**)&att,  g_att);
    cudaGetSymbolAddress((void**)&sc,   g_sc);
    cudaGetSymbolAddress((void**)&e1,   g_e1);
    cudaGetSymbolAddress((void**)&e2,   g_e2);
    cudaGetSymbolAddress((void**)&rsc,  g_rsc);

    // raise dynamic smem caps (idempotent; host-side, capture-safe)
    cudaFuncSetAttribute(tgemm<1,0,128>, cudaFuncAttributeMaxDynamicSharedMemorySize, SM_T0_128);
    cudaFuncSetAttribute(tgemm<0,0,128>, cudaFuncAttributeMaxDynamicSharedMemorySize, SM_T0_128);
    cudaFuncSetAttribute(tgemm<2,0,128>, cudaFuncAttributeMaxDynamicSharedMemorySize, SM_T0_128);
    cudaFuncSetAttribute(tgemm<0,1,128>, cudaFuncAttributeMaxDynamicSharedMemorySize, SM_T1_128);
    cudaFuncSetAttribute(tgemm<0,0,64>,  cudaFuncAttributeMaxDynamicSharedMemorySize, SM_T0_64);

    dim3 blk(256);
    const int BN = CB * CN;                          // 8192
    const long HH = (long)CHID * CHID;               // 65536

    // H = relu(x @ fc1_w + b)  [tensor core]
    tgemm<1, 0, 128><<<dim3(2, 64, 1), blk, SM_T0_128>>>(x, fc1w, fc1b, H, BN, CHID, CDIN, 0, 0, 0, 1.f);
    // P = relu(s_feature @ fc2_w + b)  [small, fp32]
    sgemm<1, 0><<<dim3(4, 1, 1), blk>>>(sf, fc2w, fc2b, nullptr, P, CB * CM, CHID, CDIN, 0, 0, 0, 1.f);

    for (int l = 0; l < CL; l++) {
        float* cur = l ? Hn : H;
        float* nxt = l ? H : Hn;

        // P_l_1 = s_adj^T @ P
        pl1_kernel<<<BN * CHID / 256, blk>>>(sadj, P, Pl1);

        // h = H @ gat_W[l]
        tgemm<0, 0, 128><<<dim3(2, 64, 1), blk, SM_T0_128>>>(cur, gatW + l * HH, nullptr, hb,
                                             BN, CHID, CHID, 0, 0, 0, 1.f);
        // edge-score ingredients
        dots_kernel<<<BN, blk>>>(hb, gata + l * 3 * CHID, gata + l * 3 * CHID + CHID, e1, e2);
        relsc_kernel<<<2, blk>>>(rel + l * 2 * CHID, gata + l * 3 * CHID + 2 * CHID, rsc);
        // masked softmax rows of att
        gat_att_kernel<<<BN, blk>>>(e1, e2, rsc, adj, smask, att);
        // Agg = elu(att @ h)   (batched over b)
        tgemm<2, 0, 128><<<dim3(2, 8, CB), blk, SM_T0_128>>>(att, hb, nullptr, Agg,
                                             CN, CHID, CN,
                                             (long)CN * CN, (long)CN * CHID, (long)CN * CHID, 1.f);
        // projections
        tgemm<0, 0, 128><<<dim3(2, 64, 1), blk, SM_T0_128>>>(cur, wv + l * HH, bv + l * CHID, Vb,
                                             BN, CHID, CHID, 0, 0, 0, 1.f);
        tgemm<0, 0, 128><<<dim3(2, 64, 1), blk, SM_T0_128>>>(Pl1, wk + l * HH, bk + l * CHID, Kb,
                                             BN, CHID, CHID, 0, 0, 0, 1.f);
        tgemm<0, 0, 128><<<dim3(2, 64, 1), blk, SM_T0_128>>>(Agg, wq + l * HH, bq + l * CHID, Qb,
                                             BN, CHID, CHID, 0, 0, 0, 1.f);
        // scores = softmax( Q @ K^T / 8 )   over 32 "heads" (contiguous reinterpret)
        tgemm<0, 1, 128><<<dim3(8, 8, CB * CNH), blk, SM_T1_128>>>(Qb, Kb, nullptr, sc,
                                                   CN, CN, CDH,
                                                   (long)CN * CDH, (long)CN * CDH,
                                                   (long)CN * CN, 0.125f);
        softmax1024<<<CB * CNH * CN, blk>>>(sc);
        // ctx = scores @ V   (TN=64 tile: no dead columns)
        tgemm<0, 0, 64><<<dim3(1, 8, CB * CNH), blk, SM_T0_64>>>(sc, Vb, nullptr, ctx,
                                                   CN, CDH, CN,
                                                   (long)CN * CN, (long)CN * CDH,
                                                   (long)CN * CDH, 1.f);
        // T = ctx @ wo + bo ;  H_new = LN(T + H)
        tgemm<0, 0, 128><<<dim3(2, 64, 1), blk, SM_T0_128>>>(ctx, wo + l * HH, bo + l * CHID, Tb,
                                             BN, CHID, CHID, 0, 0, 0, 1.f);
        ln_kernel<<<BN, blk>>>(Tb, cur, lng + l * CHID, lnb + l * CHID, nxt);

        // GRU speaker update (uses pre-update H)
        pagg_kernel<<<CB * CM, blk>>>(sadj, cur, Pagg);
        gru_kernel<<<CB * CM, blk>>>(P, Pagg,
                                     gwz + l * HH, guz + l * HH,
                                     gwr + l * HH, gur + l * HH,
                                     gw + l * HH,  gu + l * HH);
    }

    // logits = H @ out_w + out_b  (final H lives in g_H after 2 layers)
    sgemm<0, 0><<<dim3(1, 128, 1), blk>>>(H, outw, outb, nullptr, out,
                                          BN, CNC, CHID, 0, 0, 0, 1.f);
    // p_sim appended after logits
    psim_kernel<<<1, 64>>>(P, out + (long)BN * CNC, out_size - BN * CNC);
}

// round 4
// speedup vs baseline: 2.3049x; 1.1426x over previous
#include <cuda_runtime.h>
#include <math.h>
#include <stdint.h>

// ---------------- problem constants ----------------
constexpr int CB   = 8;      // batch
constexpr int CN   = 1024;   // nodes
constexpr int CM   = 8;      // speakers
constexpr int CDIN = 1024;
constexpr int CHID = 256;
constexpr int CL   = 2;
constexpr int CNC  = 7;
constexpr int CNH  = 4;
constexpr int CDH  = 64;
#define NEGF  (-9e15f)
#define ALPHAF 0.1f

// ---------------- scratch (static device memory; allocation-free) ----------------
__device__ float g_H   [CB*CN*CHID];
__device__ float g_Hn  [CB*CN*CHID];
__device__ float g_P   [CB*CM*CHID];
__device__ float g_Pagg[CB*CM*CHID];
__device__ float g_Pl1 [CB*CN*CHID];
__device__ float g_h   [CB*CN*CHID];
__device__ float g_Agg [CB*CN*CHID];
__device__ float g_Q   [CB*CN*CHID];
__device__ float g_K   [CB*CN*CHID];
__device__ float g_V   [CB*CN*CHID];
__device__ float g_ctx [CB*CN*CHID];
__device__ float g_T   [CB*CN*CHID];
__device__ float g_att [(long)CB*CN*CN];          // GAT attention  (33.5 MB)
__device__ float g_e1  [CB*CN];
__device__ float g_e2  [CB*CN];
__device__ float g_rsc [2];

// ---------------- tf32 / async helpers ----------------
__device__ __forceinline__ uint32_t f2tf(float f) {
    uint32_t u;
    asm("cvt.rna.tf32.f32 %0, %1;" : "=r"(u) : "f"(f));
    return u;
}
__device__ __forceinline__ void mma_tf32(float c[4], const uint32_t a[4], const uint32_t b[2]) {
    asm volatile(
        "mma.sync.aligned.m16n8k8.row.col.f32.tf32.tf32.f32 "
        "{%0,%1,%2,%3}, {%4,%5,%6,%7}, {%8,%9}, {%0,%1,%2,%3};\n"
        : "+f"(c[0]), "+f"(c[1]), "+f"(c[2]), "+f"(c[3])
        : "r"(a[0]), "r"(a[1]), "r"(a[2]), "r"(a[3]), "r"(b[0]), "r"(b[1]));
}
__device__ __forceinline__ void cpasync16(uint32_t saddr, const void* gptr) {
    asm volatile("cp.async.cg.shared.global [%0], [%1], 16;\n" :: "r"(saddr), "l"(gptr));
}
__device__ __forceinline__ void cpcommit() { asm volatile("cp.async.commit_group;\n"); }
__device__ __forceinline__ void cpwait0()  { asm volatile("cp.async.wait_group 0;\n"); }
__device__ __forceinline__ void cpwait1()  { asm volatile("cp.async.wait_group 1;\n"); }

// ---------------- 3-stage pipelined tf32 tensor-core GEMM ----------------
// C[M,N] = act( scale * A[M,K] @ B + bias ), B row-major [K,N].
// REQUIRES: M % 128 == 0, N % 128 == 0, K % 32 == 0.
template<int ACT>
__global__ void __launch_bounds__(256) tgemm(
    const float* __restrict__ A, const float* __restrict__ Bm,
    const float* __restrict__ bias, float* __restrict__ C,
    int M, int N, int K, long sA, long sB, long sC, float scale)
{
    constexpr int TM = 128, TN = 128, KS = 32, ST = 3;
    constexpr int strA = 36;             // words
    constexpr int strB = 132;            // words
    constexpr int AW = TM * strA;        // 4608 words/stage
    constexpr int BW = KS * strB;        // 4224 words/stage

    extern __shared__ float smem[];
    float* As = smem;                    // [ST][AW]
    float* Bs = smem + ST * AW;          // [ST][BW]
    uint32_t As_b = (uint32_t)__cvta_generic_to_shared(As);
    uint32_t Bs_b = (uint32_t)__cvta_generic_to_shared(Bs);

    int bz = blockIdx.z;
    A += (long)bz * sA;  Bm += (long)bz * sB;  C += (long)bz * sC;

    int tid  = threadIdx.x;
    int warp = tid >> 5, lane = tid & 31;
    int g = lane >> 2, tg = lane & 3;
    int mw = warp >> 2, nw = warp & 3;
    int row0 = blockIdx.y * TM, col0 = blockIdx.x * TN;

    const float* Ag = A + (long)row0 * K;
    const float* Bg = Bm + col0;

    float acc[4][4][4];
    #pragma unroll
    for (int mi = 0; mi < 4; mi++)
        #pragma unroll
        for (int ni = 0; ni < 4; ni++)
            #pragma unroll
            for (int q = 0; q < 4; q++) acc[mi][ni][q] = 0.f;

    int nk = K / KS;

    auto load_stage = [&](int kt, int s) {
        int k0 = kt * KS;
        #pragma unroll
        for (int i = 0; i < 4; i++) {
            int f = tid + i * 256;
            int m = f >> 3, k4 = (f & 7) * 4;
            cpasync16(As_b + (uint32_t)(((s * TM + m) * strA + k4) * 4),
                      Ag + (long)m * K + k0 + k4);
        }
        #pragma unroll
        for (int i = 0; i < 4; i++) {
            int f = tid + i * 256;
            int k = f >> 5, n4 = (f & 31) * 4;
            cpasync16(Bs_b + (uint32_t)(((s * KS + k) * strB + n4) * 4),
                      Bg + (long)(k0 + k) * N + n4);
        }
        cpcommit();
    };

    load_stage(0, 0);
    if (nk > 1) load_stage(1, 1);

    for (int kt = 0; kt < nk; kt++) {
        if (kt + 1 < nk) cpwait1(); else cpwait0();
        __syncthreads();
        if (kt + 2 < nk) load_stage(kt + 2, (kt + 2) % 3);

        int s = kt % 3;
        const float* Asb = As + s * AW;
        const float* Bsb = Bs + s * BW;
        #pragma unroll
        for (int ks = 0; ks < KS; ks += 8) {
            uint32_t a[4][4], b[4][2];
            #pragma unroll
            for (int mi = 0; mi < 4; mi++) {
                int mr = mw * 64 + mi * 16;
                a[mi][0] = f2tf(Asb[(mr + g)     * strA + ks + tg]);
                a[mi][1] = f2tf(Asb[(mr + g + 8) * strA + ks + tg]);
                a[mi][2] = f2tf(Asb[(mr + g)     * strA + ks + tg + 4]);
                a[mi][3] = f2tf(Asb[(mr + g + 8) * strA + ks + tg + 4]);
            }
            #pragma unroll
            for (int ni = 0; ni < 4; ni++) {
                int nc = nw * 32 + ni * 8;
                b[ni][0] = f2tf(Bsb[(ks + tg)     * strB + nc + g]);
                b[ni][1] = f2tf(Bsb[(ks + tg + 4) * strB + nc + g]);
            }
            #pragma unroll
            for (int mi = 0; mi < 4; mi++)
                #pragma unroll
                for (int ni = 0; ni < 4; ni++)
                    mma_tf32(acc[mi][ni], a[mi], b[ni]);
        }
        __syncthreads();
    }

    #pragma unroll
    for (int mi = 0; mi < 4; mi++) {
        #pragma unroll
        for (int ni = 0; ni < 4; ni++) {
            int r = row0 + mw * 64 + mi * 16 + g;
            int c = col0 + nw * 32 + ni * 8 + tg * 2;
            float b0 = bias ? bias[c] : 0.f;
            float b1 = bias ? bias[c + 1] : 0.f;
            #pragma unroll
            for (int rr = 0; rr < 2; rr++) {
                float v0 = acc[mi][ni][rr * 2 + 0] * scale + b0;
                float v1 = acc[mi][ni][rr * 2 + 1] * scale + b1;
                if (ACT == 1) { v0 = fmaxf(v0, 0.f); v1 = fmaxf(v1, 0.f); }
                else if (ACT == 2) {
                    v0 = v0 > 0.f ? v0 : expm1f(v0);
                    v1 = v1 > 0.f ? v1 : expm1f(v1);
                }
                *(float2*)(C + (long)(r + rr * 8) * N + c) = make_float2(v0, v1);
            }
        }
    }
}
constexpr int SM_TG = (3 * (128 * 36 + 32 * 132)) * 4;   // 105984 bytes

// ---------------- fused flash attention (Q@K^T/8 -> softmax -> @V) ----------------
// Per head (bh in [0,32)): Q,K,V [1024, 64] fp32 contiguous. O same layout.
// grid (8 q-blocks, 32 heads), 256 threads = 8 warps, warp owns 16 q-rows.
__global__ void __launch_bounds__(256) flash_kernel(
    const float* __restrict__ Q, const float* __restrict__ Kg_,
    const float* __restrict__ Vg_, float* __restrict__ O)
{
    constexpr int SK = 68, SV = 72;
    extern __shared__ float sm[];
    float* Qs = sm;                         // 128*68
    float* Ks = sm + 128 * SK;              // 2 * 128*68
    float* Vs = Ks + 2 * 128 * SK;          // 2 * 128*72
    uint32_t Qs_b = (uint32_t)__cvta_generic_to_shared(Qs);
    uint32_t Ks_b = (uint32_t)__cvta_generic_to_shared(Ks);
    uint32_t Vs_b = (uint32_t)__cvta_generic_to_shared(Vs);
    const uint32_t* Ku = (const uint32_t*)Ks;
    const uint32_t* Vu = (const uint32_t*)Vs;

    long base = (long)blockIdx.y * CN * CDH;
    const float* Qg = Q + base + (long)blockIdx.x * 128 * CDH;
    const float* Kg = Kg_ + base;
    const float* Vg = Vg_ + base;
    float* Og = O + base + (long)blockIdx.x * 128 * CDH;

    int tid = threadIdx.x, warp = tid >> 5, lane = tid & 31;
    int g = lane >> 2, tg = lane & 3;
    int r0 = warp * 16;

    // load Q tile (group 0)
    #pragma unroll
    for (int i = 0; i < 8; i++) {
        int f = tid + i * 256;
        int r = f >> 4, c4 = (f & 15) * 4;
        cpasync16(Qs_b + (uint32_t)((r * SK + c4) * 4), Qg + r * CDH + c4);
    }
    cpcommit();

    auto load_kv = [&](int t, int s) {
        const float* Kt = Kg + t * 128 * CDH;
        const float* Vt = Vg + t * 128 * CDH;
        #pragma unroll
        for (int i = 0; i < 8; i++) {
            int f = tid + i * 256;
            int r = f >> 4, c4 = (f & 15) * 4;
            cpasync16(Ks_b + (uint32_t)(((s * 128 + r) * SK + c4) * 4), Kt + r * CDH + c4);
            cpasync16(Vs_b + (uint32_t)(((s * 128 + r) * SV + c4) * 4), Vt + r * CDH + c4);
        }
        cpcommit();
    };
    load_kv(0, 0);

    cpwait1();            // Q done
    __syncthreads();

    // Q fragments to registers (read once)
    uint32_t aq[8][4];
    #pragma unroll
    for (int kf = 0; kf < 8; kf++) {
        aq[kf][0] = f2tf(Qs[(r0 + g)     * SK + kf * 8 + tg]);
        aq[kf][1] = f2tf(Qs[(r0 + g + 8) * SK + kf * 8 + tg]);
        aq[kf][2] = f2tf(Qs[(r0 + g)     * SK + kf * 8 + tg + 4]);
        aq[kf][3] = f2tf(Qs[(r0 + g + 8) * SK + kf * 8 + tg + 4]);
    }

    float m0 = -3.4e38f, m1 = -3.4e38f, l0 = 0.f, l1 = 0.f;
    float o[8][4];
    #pragma unroll
    for (int nf = 0; nf < 8; nf++)
        #pragma unroll
        for (int q = 0; q < 4; q++) o[nf][q] = 0.f;

    for (int t = 0; t < 8; t++) {
        int s = t & 1;
        if (t < 7) load_kv(t + 1, s ^ 1);
        if (t < 7) cpwait1(); else cpwait0();
        __syncthreads();
        // convert K,V stage s fp32 -> tf32 in place (shared work)
        #pragma unroll
        for (int i = 0; i < 8; i++) {
            int f = tid + i * 256;
            int r = f >> 4, c4 = (f & 15) * 4;
            float4* kp = (float4*)&Ks[(s * 128 + r) * SK + c4];
            float4 kv = *kp;
            uint4 ko = make_uint4(f2tf(kv.x), f2tf(kv.y), f2tf(kv.z), f2tf(kv.w));
            *(uint4*)kp = ko;
            float4* vp = (float4*)&Vs[(s * 128 + r) * SV + c4];
            float4 vv = *vp;
            uint4 vo = make_uint4(f2tf(vv.x), f2tf(vv.y), f2tf(vv.z), f2tf(vv.w));
            *(uint4*)vp = vo;
        }
        __syncthreads();

        // S = Q @ K^T  (per-warp [16,128])
        float sc[16][4];
        #pragma unroll
        for (int nf = 0; nf < 16; nf++)
            #pragma unroll
            for (int q = 0; q < 4; q++) sc[nf][q] = 0.f;
        #pragma unroll
        for (int kf = 0; kf < 8; kf++) {
            #pragma unroll
            for (int nf = 0; nf < 16; nf++) {
                uint32_t b[2];
                b[0] = Ku[(s * 128 + nf * 8 + g) * SK + kf * 8 + tg];
                b[1] = Ku[(s * 128 + nf * 8 + g) * SK + kf * 8 + tg + 4];
                mma_tf32(sc[nf], aq[kf], b);
            }
        }

        // online softmax (scaled by 1/8)
        float mx0 = -3.4e38f, mx1 = -3.4e38f;
        #pragma unroll
        for (int nf = 0; nf < 16; nf++) {
            mx0 = fmaxf(mx0, fmaxf(sc[nf][0], sc[nf][1]));
            mx1 = fmaxf(mx1, fmaxf(sc[nf][2], sc[nf][3]));
        }
        #pragma unroll
        for (int off = 1; off <= 2; off <<= 1) {
            mx0 = fmaxf(mx0, __shfl_xor_sync(0xffffffffu, mx0, off));
            mx1 = fmaxf(mx1, __shfl_xor_sync(0xffffffffu, mx1, off));
        }
        float mn0 = fmaxf(m0, mx0 * 0.125f);
        float mn1 = fmaxf(m1, mx1 * 0.125f);
        float cr0 = __expf(m0 - mn0);
        float cr1 = __expf(m1 - mn1);
        l0 *= cr0; l1 *= cr1;
        #pragma unroll
        for (int nf = 0; nf < 8; nf++) {
            o[nf][0] *= cr0; o[nf][1] *= cr0;
            o[nf][2] *= cr1; o[nf][3] *= cr1;
        }
        float rs0 = 0.f, rs1 = 0.f;
        #pragma unroll
        for (int nf = 0; nf < 16; nf++) {
            float p0 = __expf(sc[nf][0] * 0.125f - mn0);
            float p1 = __expf(sc[nf][1] * 0.125f - mn0);
            float p2 = __expf(sc[nf][2] * 0.125f - mn1);
            float p3 = __expf(sc[nf][3] * 0.125f - mn1);
            rs0 += p0 + p1;  rs1 += p2 + p3;
            sc[nf][0] = __uint_as_float(f2tf(p0));
            sc[nf][1] = __uint_as_float(f2tf(p1));
            sc[nf][2] = __uint_as_float(f2tf(p2));
            sc[nf][3] = __uint_as_float(f2tf(p3));
        }
        #pragma unroll
        for (int off = 1; off <= 2; off <<= 1) {
            rs0 += __shfl_xor_sync(0xffffffffu, rs0, off);
            rs1 += __shfl_xor_sync(0xffffffffu, rs1, off);
        }
        l0 += rs0; l1 += rs1; m0 = mn0; m1 = mn1;

        // O += P @ V : gather A-frags of P via intra-quad shuffles
        int srcA = (g << 2) + (tg >> 1);
        int srcB = srcA + 2;
        bool odd = tg & 1;
        #pragma unroll
        for (int kf = 0; kf < 16; kf++) {
            float u0 = __shfl_sync(0xffffffffu, sc[kf][0], srcA);
            float u1 = __shfl_sync(0xffffffffu, sc[kf][1], srcA);
            float u2 = __shfl_sync(0xffffffffu, sc[kf][2], srcA);
            float u3 = __shfl_sync(0xffffffffu, sc[kf][3], srcA);
            float w0 = __shfl_sync(0xffffffffu, sc[kf][0], srcB);
            float w1 = __shfl_sync(0xffffffffu, sc[kf][1], srcB);
            float w2 = __shfl_sync(0xffffffffu, sc[kf][2], srcB);
            float w3 = __shfl_sync(0xffffffffu, sc[kf][3], srcB);
            uint32_t a[4];
            a[0] = __float_as_uint(odd ? u1 : u0);   // (row g,   col 8kf+tg)
            a[1] = __float_as_uint(odd ? u3 : u2);   // (row g+8, col 8kf+tg)
            a[2] = __float_as_uint(odd ? w1 : w0);   // (row g,   col 8kf+tg+4)
            a[3] = __float_as_uint(odd ? w3 : w2);   // (row g+8, col 8kf+tg+4)
            #pragma unroll
            for (int nf = 0; nf < 8; nf++) {
                uint32_t b[2];
                b[0] = Vu[(s * 128 + kf * 8 + tg)     * SV + nf * 8 + g];
                b[1] = Vu[(s * 128 + kf * 8 + tg + 4) * SV + nf * 8 + g];
                mma_tf32(o[nf], a, b);
            }
        }
        __syncthreads();   // stage s free before prefetch (t+1 issues into s at t+1)
    }

    float inv0 = 1.f / l0, inv1 = 1.f / l1;
    #pragma unroll
    for (int nf = 0; nf < 8; nf++) {
        int c = nf * 8 + tg * 2;
        *(float2*)(Og + (long)(r0 + g)     * CDH + c) = make_float2(o[nf][0] * inv0, o[nf][1] * inv0);
        *(float2*)(Og + (long)(r0 + g + 8) * CDH + c) = make_float2(o[nf][2] * inv1, o[nf][3] * inv1);
    }
}
constexpr int SM_FLASH = (128 * 68 + 2 * 128 * 68 + 2 * 128 * 72) * 4;   // 178176

// ---------------- fp32 tiled SGEMM (fc2 only) ----------------
template<int ACT>
__global__ void sgemm(const float* __restrict__ A, const float* __restrict__ Bm,
                      const float* __restrict__ bias, float* __restrict__ C,
                      int M, int N, int K)
{
    __shared__ float As[16][68];
    __shared__ float Bs[16][68];
    int tx = threadIdx.x;
    int tr = tx >> 4, tc = tx & 15;
    int row0 = blockIdx.y * 64, col0 = blockIdx.x * 64;

    float acc[4][4] = {};
    for (int k0 = 0; k0 < K; k0 += 16) {
        #pragma unroll
        for (int i = 0; i < 4; i++) {
            int idx = tx * 4 + i;
            int m = idx >> 4, k = idx & 15;
            int gr = row0 + m;
            As[k][m] = (gr < M) ? A[(long)gr * K + k0 + k] : 0.f;
        }
        #pragma unroll
        for (int i = 0; i < 4; i++) {
            int idx = tx * 4 + i;
            int k = idx >> 6, n = idx & 63;
            int gn = col0 + n;
            Bs[k][n] = (gn < N) ? Bm[(long)(k0 + k) * N + gn] : 0.f;
        }
        __syncthreads();
        #pragma unroll
        for (int k = 0; k < 16; k++) {
            float a[4], b[4];
            #pragma unroll
            for (int i = 0; i < 4; i++) a[i] = As[k][tr * 4 + i];
            #pragma unroll
            for (int j = 0; j < 4; j++) b[j] = Bs[k][tc * 4 + j];
            #pragma unroll
            for (int i = 0; i < 4; i++)
                #pragma unroll
                for (int j = 0; j < 4; j++)
                    acc[i][j] = fmaf(a[i], b[j], acc[i][j]);
        }
        __syncthreads();
    }
    #pragma unroll
    for (int i = 0; i < 4; i++) {
        int gr = row0 + tr * 4 + i;
        if (gr >= M) continue;
        #pragma unroll
        for (int j = 0; j < 4; j++) {
            int gn = col0 + tc * 4 + j;
            if (gn >= N) continue;
            float v = acc[i][j];
            if (bias) v += bias[gn];
            if (ACT == 1) v = v > 0.f ? v : 0.f;
            C[(long)gr * N + gn] = v;
        }
    }
}

// ---------------- logits: warp per row, N=7 ----------------
__global__ void logits_kernel(const float* __restrict__ H, const float* __restrict__ W,
                              const float* __restrict__ bb, float* __restrict__ out)
{
    int warp = threadIdx.x >> 5, lane = threadIdx.x & 31;
    int row = blockIdx.x * 8 + warp;
    float hv[8];
    #pragma unroll
    for (int j = 0; j < 8; j++) hv[j] = H[(long)row * CHID + j * 32 + lane];
    float acc[CNC];
    #pragma unroll
    for (int c = 0; c < CNC; c++) {
        float a = 0.f;
        #pragma unroll
        for (int j = 0; j < 8; j++) a = fmaf(hv[j], W[(j * 32 + lane) * CNC + c], a);
        acc[c] = a;
    }
    #pragma unroll
    for (int c = 0; c < CNC; c++)
        #pragma unroll
        for (int off = 16; off > 0; off >>= 1)
            acc[c] += __shfl_xor_sync(0xffffffffu, acc[c], off);
    if (lane < CNC) out[(long)row * CNC + lane] = acc[lane] + bb[lane];
}

// ---------------- P_l_1[b,n,d] = sum_m s_adj[b,m,n] * P[b,m,d] ----------------
__global__ void pl1_kernel(const float* __restrict__ sadj, const float* __restrict__ P,
                           float* __restrict__ out)
{
    long idx = (long)blockIdx.x * 256 + threadIdx.x;
    int d = idx & (CHID - 1);
    int n = (idx >> 8) & (CN - 1);
    int b = (int)(idx >> 18);
    const float* sa = sadj + (long)b * CM * CN + n;
    const float* Pb = P + (long)b * CM * CHID + d;
    float acc = 0.f;
    #pragma unroll
    for (int m = 0; m < CM; m++) acc = fmaf(sa[m * CN], Pb[m * CHID], acc);
    out[idx] = acc;
}

// ---------------- P_agg[b,m,d] = sum_n s_adj[b,m,n] * H[b,n,d] ----------------
__global__ void pagg_kernel(const float* __restrict__ sadj, const float* __restrict__ H,
                            float* __restrict__ out)
{
    int bm = blockIdx.x;
    int b = bm >> 3;
    int d = threadIdx.x;
    const float* sa = sadj + (long)bm * CN;
    const float* Hb = H + (long)b * CN * CHID + d;
    float acc = 0.f;
    #pragma unroll 4
    for (int n = 0; n < CN; n++) acc = fmaf(sa[n], Hb[(long)n * CHID], acc);
    out[(long)bm * CHID + d] = acc;
}

// ---------------- e1/e2: per-row dots of h with a1, a2 ----------------
__global__ void dots_kernel(const float* __restrict__ h, const float* __restrict__ a1,
                            const float* __restrict__ a2,
                            float* __restrict__ e1, float* __restrict__ e2)
{
    __shared__ float s1[256], s2[256];
    int row = blockIdx.x, t = threadIdx.x;
    float v = h[(long)row * CHID + t];
    s1[t] = v * a1[t];
    s2[t] = v * a2[t];
    __syncthreads();
    for (int o = 128; o > 0; o >>= 1) {
        if (t < o) { s1[t] += s1[t + o]; s2[t] += s2[t + o]; }
        __syncthreads();
    }
    if (t == 0) { e1[row] = s1[0]; e2[row] = s2[0]; }
}

// ---------------- rel_sc[r] = dot(rel_emb[l][r], a3) ----------------
__global__ void relsc_kernel(const float* __restrict__ rel, const float* __restrict__ a3,
                             float* __restrict__ out)
{
    __shared__ float s[256];
    int r = blockIdx.x, t = threadIdx.x;
    s[t] = rel[r * CHID + t] * a3[t];
    __syncthreads();
    for (int o = 128; o > 0; o >>= 1) {
        if (t < o) s[t] += s[t + o];
        __syncthreads();
    }
    if (t == 0) out[r] = s[0];
}

// ---------------- GAT edge scores + masked softmax, one row per block ----------------
__global__ void gat_att_kernel(const float* __restrict__ e1, const float* __restrict__ e2,
                               const float* __restrict__ rsc,
                               const int* __restrict__ adj, const int* __restrict__ smask,
                               float* __restrict__ att)
{
    __shared__ float red[256];
    int bi = blockIdx.x;
    int b = bi >> 10;
    long base = (long)bi * CN;
    int t = threadIdx.x;
    float E1 = e1[bi];
    const float* e2b = e2 + b * CN;

    float vals[4];
    float mx = -3.4e38f;
    #pragma unroll
    for (int q = 0; q < 4; q++) {
        int j = t + q * 256;
        float e = E1 + e2b[j] + rsc[smask[base + j]];
        e = e >= 0.f ? e : ALPHAF * e;
        e = (adj[base + j] > 0) ? e : NEGF;
        vals[q] = e;
        mx = fmaxf(mx, e);
    }
    red[t] = mx; __syncthreads();
    for (int o = 128; o > 0; o >>= 1) {
        if (t < o) red[t] = fmaxf(red[t], red[t + o]);
        __syncthreads();
    }
    mx = red[0]; __syncthreads();
    float s = 0.f;
    #pragma unroll
    for (int q = 0; q < 4; q++) { vals[q] = expf(vals[q] - mx); s += vals[q]; }
    red[t] = s; __syncthreads();
    for (int o = 128; o > 0; o >>= 1) {
        if (t < o) red[t] += red[t + o];
        __syncthreads();
    }
    float inv = 1.f / red[0];
    #pragma unroll
    for (int q = 0; q < 4; q++) att[base + t + q * 256] = vals[q] * inv;
}

// ---------------- LayerNorm( T + Hold ) * g + b ----------------
__global__ void ln_kernel(const float* __restrict__ T, const float* __restrict__ Hold,
                          const float* __restrict__ g, const float* __restrict__ bb,
                          float* __restrict__ out)
{
    __shared__ float red[256];
    int row = blockIdx.x, t = threadIdx.x;
    long off = (long)row * CHID + t;
    float v = T[off] + Hold[off];
    red[t] = v; __syncthreads();
    for (int o = 128; o > 0; o >>= 1) {
        if (t < o) red[t] += red[t + o];
        __syncthreads();
    }
    float mu = red[0] * (1.f / CHID);
    __syncthreads();
    float dv = v - mu;
    red[t] = dv * dv; __syncthreads();
    for (int o = 128; o > 0; o >>= 1) {
        if (t < o) red[t] += red[t + o];
        __syncthreads();
    }
    float var = red[0] * (1.f / CHID);
    out[off] = dv * rsqrtf(var + 1e-5f) * g[t] + bb[t];
}

// ---------------- GRU3d: in-place update of P (one row per block) ----------------
__global__ void gru_kernel(float* __restrict__ P, const float* __restrict__ Pagg,
                           const float* __restrict__ wz, const float* __restrict__ uz,
                           const float* __restrict__ wr, const float* __restrict__ ur,
                           const float* __restrict__ w,  const float* __restrict__ u)
{
    __shared__ float sp[CHID], sq[CHID];
    int r = blockIdx.x;
    int c = threadIdx.x;
    sp[c] = P[(long)r * CHID + c];
    sq[c] = Pagg[(long)r * CHID + c];
    __syncthreads();
    float az = 0, bz = 0, ar = 0, br = 0, aw = 0, bw = 0;
    for (int k = 0; k < CHID; k++) {
        float pk = sp[k], qk = sq[k];
        az = fmaf(pk, wz[k * CHID + c], az); bz = fmaf(qk, uz[k * CHID + c], bz);
        ar = fmaf(pk, wr[k * CHID + c], ar); br = fmaf(qk, ur[k * CHID + c], br);
        aw = fmaf(pk, w [k * CHID + c], aw); bw = fmaf(qk, u [k * CHID + c], bw);
    }
    float z  = 1.f / (1.f + expf(-(az + bz)));
    float rr = 1.f / (1.f + expf(-(ar + br)));
    float hh = tanhf(aw + rr * bw);
    P[(long)r * CHID + c] = (1.f - z) * sp[c] + z * hh;
}

// ---------------- p_sim ----------------
__global__ void psim_kernel(const float* __restrict__ P, float* __restrict__ outp, int tail)
{
    __shared__ float red[64];
    int t = threadIdx.x;
    int b = t >> 3, m = t & 7;
    const float* Pb = P + (long)b * CM * CHID;
    float s = 0.f;
    for (int k2 = 0; k2 < CM; k2++) {
        if (k2 == m) continue;
        float d = 0.f;
        for (int dd = 0; dd < CHID; dd++)
            d = fmaf(Pb[m * CHID + dd], Pb[k2 * CHID + dd], d);
        s += d;
    }
    red[t] = s; __syncthreads();
    if ((t & 7) < 4) red[t] += red[t + 4]; __syncthreads();
    if ((t & 7) < 2) red[t] += red[t + 2]; __syncthreads();
    if ((t & 7) < 1) red[t] += red[t + 1]; __syncthreads();
    if (tail >= CB) {
        if (t < CB) outp[t] = red[t * 8] / (float)(CM * CM);
    } else {
        if (t == 0) {
            float tot = 0.f;
            for (int b2 = 0; b2 < CB; b2++) tot += red[b2 * 8];
            outp[0] = tot / (float)(CB * CM * CM);
        }
    }
}

// ---------------- host orchestration ----------------
extern "C" void kernel_launch(void* const* d_in, const int* in_sizes, int n_in,
                              void* d_out, int out_size)
{
    const float* x     = (const float*)d_in[0];
    const int*   adj   = (const int*)  d_in[1];
    const int*   smask = (const int*)  d_in[2];
    const float* sf    = (const float*)d_in[3];
    const float* sadj  = (const float*)d_in[4];
    const float* fc1w  = (const float*)d_in[6];
    const float* fc1b  = (const float*)d_in[7];
    const float* fc2w  = (const float*)d_in[8];
    const float* fc2b  = (const float*)d_in[9];
    const float* gatW  = (const float*)d_in[10];
    const float* gata  = (const float*)d_in[11];
    const float* rel   = (const float*)d_in[12];
    const float* gwz   = (const float*)d_in[13];
    const float* guz   = (const float*)d_in[14];
    const float* gwr   = (const float*)d_in[15];
    const float* gur   = (const float*)d_in[16];
    const float* gw    = (const float*)d_in[17];
    const float* gu    = (const float*)d_in[18];
    const float* wv    = (const float*)d_in[19];
    const float* bv    = (const float*)d_in[20];
    const float* wk    = (const float*)d_in[21];
    const float* bk    = (const float*)d_in[22];
    const float* wq    = (const float*)d_in[23];
    const float* bq    = (const float*)d_in[24];
    const float* wo    = (const float*)d_in[25];
    const float* bo    = (const float*)d_in[26];
    const float* lng   = (const float*)d_in[27];
    const float* lnb   = (const float*)d_in[28];
    const float* outw  = (const float*)d_in[29];
    const float* outb  = (const float*)d_in[30];
    float* out = (float*)d_out;

    float *H, *Hn, *P, *Pagg, *Pl1, *hb, *Agg, *Qb, *Kb, *Vb, *ctx, *Tb, *att, *e1, *e2, *rsc;
    cudaGetSymbolAddress((void**)&H,    g_H);
    cudaGetSymbolAddress((void**)&Hn,   g_Hn);
    cudaGetSymbolAddress((void**)&P,    g_P);
    cudaGetSymbolAddress((void**)&Pagg, g_Pagg);
    cudaGetSymbolAddress((void**)&Pl1,  g_Pl1);
    cudaGetSymbolAddress((void**)&hb,   g_h);
    cudaGetSymbolAddress((void**)&Agg,  g_Agg);
    cudaGetSymbolAddress((void**)&Qb,   g_Q);
    cudaGetSymbolAddress((void**)&Kb,   g_K);
    cudaGetSymbolAddress((void**)&Vb,   g_V);
    cudaGetSymbolAddress((void**)&ctx,  g_ctx);
    cudaGetSymbolAddress((void**)&Tb,   g_T);
    cudaGetSymbolAddress((void**)&att,  g_att);
    cudaGetSymbolAddress((void**)&e1,   g_e1);
    cudaGetSymbolAddress((void**)&e2,   g_e2);
    cudaGetSymbolAddress((void**)&rsc,  g_rsc);

    cudaFuncSetAttribute(tgemm<0>, cudaFuncAttributeMaxDynamicSharedMemorySize, SM_TG);
    cudaFuncSetAttribute(tgemm<1>, cudaFuncAttributeMaxDynamicSharedMemorySize, SM_TG);
    cudaFuncSetAttribute(tgemm<2>, cudaFuncAttributeMaxDynamicSharedMemorySize, SM_TG);
    cudaFuncSetAttribute(flash_kernel, cudaFuncAttributeMaxDynamicSharedMemorySize, SM_FLASH);

    dim3 blk(256);
    const int BN = CB * CN;                          // 8192
    const long HH = (long)CHID * CHID;               // 65536

    // H = relu(x @ fc1_w + b)
    tgemm<1><<<dim3(2, 64, 1), blk, SM_TG>>>(x, fc1w, fc1b, H, BN, CHID, CDIN, 0, 0, 0, 1.f);
    // P = relu(s_feature @ fc2_w + b)
    sgemm<1><<<dim3(4, 1, 1), blk>>>(sf, fc2w, fc2b, P, CB * CM, CHID, CDIN);

    for (int l = 0; l < CL; l++) {
        float* cur = l ? Hn : H;
        float* nxt = l ? H : Hn;

        // P_l_1 = s_adj^T @ P
        pl1_kernel<<<BN * CHID / 256, blk>>>(sadj, P, Pl1);

        // h = H @ gat_W[l]
        tgemm<0><<<dim3(2, 64, 1), blk, SM_TG>>>(cur, gatW + l * HH, nullptr, hb,
                                                 BN, CHID, CHID, 0, 0, 0, 1.f);
        // edge-score ingredients
        dots_kernel<<<BN, blk>>>(hb, gata + l * 3 * CHID, gata + l * 3 * CHID + CHID, e1, e2);
        relsc_kernel<<<2, blk>>>(rel + l * 2 * CHID, gata + l * 3 * CHID + 2 * CHID, rsc);
        // masked softmax rows of att
        gat_att_kernel<<<BN, blk>>>(e1, e2, rsc, adj, smask, att);
        // Agg = elu(att @ h)
        tgemm<2><<<dim3(2, 8, CB), blk, SM_TG>>>(att, hb, nullptr, Agg,
                                                 CN, CHID, CN,
                                                 (long)CN * CN, (long)CN * CHID, (long)CN * CHID, 1.f);
        // projections
        tgemm<0><<<dim3(2, 64, 1), blk, SM_TG>>>(cur, wv + l * HH, bv + l * CHID, Vb,
                                                 BN, CHID, CHID, 0, 0, 0, 1.f);
        tgemm<0><<<dim3(2, 64, 1), blk, SM_TG>>>(Pl1, wk + l * HH, bk + l * CHID, Kb,
                                                 BN, CHID, CHID, 0, 0, 0, 1.f);
        tgemm<0><<<dim3(2, 64, 1), blk, SM_TG>>>(Agg, wq + l * HH, bq + l * CHID, Qb,
                                                 BN, CHID, CHID, 0, 0, 0, 1.f);
        // fused MHA: ctx = softmax(Q K^T / 8) V over 32 head-batches
        flash_kernel<<<dim3(8, 32), blk, SM_FLASH>>>(Qb, Kb, Vb, ctx);
        // T = ctx @ wo + bo ;  H_new = LN(T + H)
        tgemm<0><<<dim3(2, 64, 1), blk, SM_TG>>>(ctx, wo + l * HH, bo + l * CHID, Tb,
                                                 BN, CHID, CHID, 0, 0, 0, 1.f);
        ln_kernel<<<BN, blk>>>(Tb, cur, lng + l * CHID, lnb + l * CHID, nxt);

        // GRU speaker update (uses pre-update H)
        pagg_kernel<<<CB * CM, blk>>>(sadj, cur, Pagg);
        gru_kernel<<<CB * CM, blk>>>(P, Pagg,
                                     gwz + l * HH, guz + l * HH,
                                     gwr + l * HH, gur + l * HH,
                                     gw + l * HH,  gu + l * HH);
    }

    // logits = H @ out_w + out_b
    logits_kernel<<<BN / 8, blk>>>(H, outw, outb, out);
    // p_sim appended after logits
    psim_kernel<<<1, 64>>>(P, out + (long)BN * CNC, out_size - BN * CNC);
}

// round 5
// speedup vs baseline: 2.3548x; 1.0217x over previous
#include <cuda_runtime.h>
#include <math.h>
#include <stdint.h>

// ---------------- problem constants ----------------
constexpr int CB   = 8;      // batch
constexpr int CN   = 1024;   // nodes
constexpr int CM   = 8;      // speakers
constexpr int CDIN = 1024;
constexpr int CHID = 256;
constexpr int CL   = 2;
constexpr int CNC  = 7;
constexpr int CNH  = 4;
constexpr int CDH  = 64;
#define NEGF  (-9e15f)
#define ALPHAF 0.1f

// ---------------- scratch ----------------
__device__ float g_H   [CB*CN*CHID];
__device__ float g_Hn  [CB*CN*CHID];
__device__ float g_P   [CB*CM*CHID];
__device__ float g_Pagg[CB*CM*CHID];
__device__ float g_Pl1 [CB*CN*CHID];
__device__ float g_h   [CB*CN*CHID];
__device__ float g_Agg [CB*CN*CHID];
__device__ float g_Q   [CB*CN*CHID];
__device__ float g_K   [CB*CN*CHID];
__device__ float g_V   [CB*CN*CHID];
__device__ float g_ctx [CB*CN*CHID];
__device__ float g_T   [CB*CN*CHID];
__device__ float g_att [(long)CB*CN*CN];
__device__ float g_e1  [CB*CN];
__device__ float g_e2  [CB*CN];
__device__ float g_rsc [2];

// ---------------- tf32 / async helpers ----------------
__device__ __forceinline__ uint32_t f2tf(float f) {
    uint32_t u;
    asm("cvt.rna.tf32.f32 %0, %1;" : "=r"(u) : "f"(f));
    return u;
}
__device__ __forceinline__ void mma_tf32(float c[4], const uint32_t a[4], const uint32_t b[2]) {
    asm volatile(
        "mma.sync.aligned.m16n8k8.row.col.f32.tf32.tf32.f32 "
        "{%0,%1,%2,%3}, {%4,%5,%6,%7}, {%8,%9}, {%0,%1,%2,%3};\n"
        : "+f"(c[0]), "+f"(c[1]), "+f"(c[2]), "+f"(c[3])
        : "r"(a[0]), "r"(a[1]), "r"(a[2]), "r"(a[3]), "r"(b[0]), "r"(b[1]));
}
__device__ __forceinline__ void cpasync16(uint32_t saddr, const void* gptr) {
    asm volatile("cp.async.cg.shared.global [%0], [%1], 16;\n" :: "r"(saddr), "l"(gptr));
}
__device__ __forceinline__ void cpcommit() { asm volatile("cp.async.commit_group;\n"); }
__device__ __forceinline__ void cpwait0()  { asm volatile("cp.async.wait_group 0;\n"); }
__device__ __forceinline__ void cpwait1()  { asm volatile("cp.async.wait_group 1;\n"); }

// ================= core GEMM tile machinery (128x128, KS=32, 3-stage) =================
struct TileCtx {
    float *As, *Bs;
    uint32_t As_b, Bs_b;
    const float *Ag, *Bg;
    int K, N;
    int tid;
};
constexpr int T_strA = 36, T_strB = 132;
constexpr int T_AW = 128 * T_strA, T_BW = 32 * T_strB;
constexpr int SM_TG = (3 * (T_AW + T_BW)) * 4;   // 105984 bytes

__device__ __forceinline__ void tg_load_stage(TileCtx& c, int kt, int s) {
    int k0 = kt * 32;
    #pragma unroll
    for (int i = 0; i < 4; i++) {
        int f = c.tid + i * 256;
        int m = f >> 3, k4 = (f & 7) * 4;
        cpasync16(c.As_b + (uint32_t)(((s * 128 + m) * T_strA + k4) * 4),
                  c.Ag + (long)m * c.K + k0 + k4);
    }
    #pragma unroll
    for (int i = 0; i < 4; i++) {
        int f = c.tid + i * 256;
        int k = f >> 5, n4 = (f & 31) * 4;
        cpasync16(c.Bs_b + (uint32_t)(((s * 32 + k) * T_strB + n4) * 4),
                  c.Bg + (long)(k0 + k) * c.N + n4);
    }
    cpcommit();
}

template<int ACT>
__device__ __forceinline__ void tg_body(
    TileCtx& c, const float* bias, float* C, int M, int N, int K,
    int row0, int col0, float scale)
{
    int tid  = c.tid;
    int warp = tid >> 5, lane = tid & 31;
    int g = lane >> 2, tg = lane & 3;
    int mw = warp >> 2, nw = warp & 3;

    float acc[4][4][4];
    #pragma unroll
    for (int mi = 0; mi < 4; mi++)
        #pragma unroll
        for (int ni = 0; ni < 4; ni++)
            #pragma unroll
            for (int q = 0; q < 4; q++) acc[mi][ni][q] = 0.f;

    int nk = K / 32;
    tg_load_stage(c, 0, 0);
    if (nk > 1) tg_load_stage(c, 1, 1);

    for (int kt = 0; kt < nk; kt++) {
        if (kt + 1 < nk) cpwait1(); else cpwait0();
        __syncthreads();
        if (kt + 2 < nk) tg_load_stage(c, kt + 2, (kt + 2) % 3);

        int s = kt % 3;
        const float* Asb = c.As + s * T_AW;
        const float* Bsb = c.Bs + s * T_BW;
        #pragma unroll
        for (int ks = 0; ks < 32; ks += 8) {
            uint32_t a[4][4], b[4][2];
            #pragma unroll
            for (int mi = 0; mi < 4; mi++) {
                int mr = mw * 64 + mi * 16;
                a[mi][0] = f2tf(Asb[(mr + g)     * T_strA + ks + tg]);
                a[mi][1] = f2tf(Asb[(mr + g + 8) * T_strA + ks + tg]);
                a[mi][2] = f2tf(Asb[(mr + g)     * T_strA + ks + tg + 4]);
                a[mi][3] = f2tf(Asb[(mr + g + 8) * T_strA + ks + tg + 4]);
            }
            #pragma unroll
            for (int ni = 0; ni < 4; ni++) {
                int nc = nw * 32 + ni * 8;
                b[ni][0] = f2tf(Bsb[(ks + tg)     * T_strB + nc + g]);
                b[ni][1] = f2tf(Bsb[(ks + tg + 4) * T_strB + nc + g]);
            }
            #pragma unroll
            for (int mi = 0; mi < 4; mi++)
                #pragma unroll
                for (int ni = 0; ni < 4; ni++)
                    mma_tf32(acc[mi][ni], a[mi], b[ni]);
        }
        __syncthreads();
    }

    #pragma unroll
    for (int mi = 0; mi < 4; mi++) {
        #pragma unroll
        for (int ni = 0; ni < 4; ni++) {
            int r = row0 + mw * 64 + mi * 16 + g;
            int cc0 = col0 + nw * 32 + ni * 8 + tg * 2;
            float b0 = bias ? bias[cc0] : 0.f;
            float b1 = bias ? bias[cc0 + 1] : 0.f;
            #pragma unroll
            for (int rr = 0; rr < 2; rr++) {
                float v0 = acc[mi][ni][rr * 2 + 0] * scale + b0;
                float v1 = acc[mi][ni][rr * 2 + 1] * scale + b1;
                if (ACT == 1) { v0 = fmaxf(v0, 0.f); v1 = fmaxf(v1, 0.f); }
                else if (ACT == 2) {
                    v0 = v0 > 0.f ? v0 : expm1f(v0);
                    v1 = v1 > 0.f ? v1 : expm1f(v1);
                }
                *(float2*)(C + (long)(r + rr * 8) * N + cc0) = make_float2(v0, v1);
            }
        }
    }
}

// ---------------- single GEMM (batched via strides) ----------------
template<int ACT>
__global__ void __launch_bounds__(256) tgemm(
    const float* __restrict__ A, const float* __restrict__ Bm,
    const float* __restrict__ bias, float* __restrict__ C,
    int M, int N, int K, long sA, long sB, long sC, float scale)
{
    extern __shared__ float smem[];
    int bz = blockIdx.z;
    TileCtx c;
    c.As = smem; c.Bs = smem + 3 * T_AW;
    c.As_b = (uint32_t)__cvta_generic_to_shared(c.As);
    c.Bs_b = (uint32_t)__cvta_generic_to_shared(c.Bs);
    c.K = K; c.N = N; c.tid = threadIdx.x;
    int row0 = blockIdx.y * 128, col0 = blockIdx.x * 128;
    const float* Ab = A + (long)bz * sA;
    const float* Bb = Bm + (long)bz * sB;
    c.Ag = Ab + (long)row0 * K;
    c.Bg = Bb + col0;
    tg_body<ACT>(c, bias, C + (long)bz * sC, M, N, K, row0, col0, scale);
}

// ---------------- paired GEMM: z selects {A,B,bias,C} ----------------
struct G2 { const float* A[2]; const float* B[2]; const float* bias[2]; float* C[2]; };
__global__ void __launch_bounds__(256) tgemm_pair(G2 args, int M, int N, int K)
{
    extern __shared__ float smem[];
    int z = blockIdx.z;
    TileCtx c;
    c.As = smem; c.Bs = smem + 3 * T_AW;
    c.As_b = (uint32_t)__cvta_generic_to_shared(c.As);
    c.Bs_b = (uint32_t)__cvta_generic_to_shared(c.Bs);
    c.K = K; c.N = N; c.tid = threadIdx.x;
    int row0 = blockIdx.y * 128, col0 = blockIdx.x * 128;
    c.Ag = args.A[z] + (long)row0 * K;
    c.Bg = args.B[z] + col0;
    tg_body<0>(c, args.bias[z], args.C[z], M, N, K, row0, col0, 1.f);
}

// ---------------- fused flash attention, 64-row KV tiles ----------------
// grid (8 q-blocks, 32 heads), 256 threads = 8 warps, warp owns 16 q-rows.
__global__ void __launch_bounds__(256, 2) flash_kernel(
    const float* __restrict__ Q, const float* __restrict__ Kg_,
    const float* __restrict__ Vg_, float* __restrict__ O)
{
    constexpr int SK = 68, SV = 72, KT = 64;
    extern __shared__ float sm[];
    float* Qs = sm;                          // 128*68
    float* Ks = sm + 128 * SK;               // 2 * 64*68
    float* Vs = Ks + 2 * KT * SK;            // 2 * 64*72
    uint32_t Qs_b = (uint32_t)__cvta_generic_to_shared(Qs);
    uint32_t Ks_b = (uint32_t)__cvta_generic_to_shared(Ks);
    uint32_t Vs_b = (uint32_t)__cvta_generic_to_shared(Vs);
    const uint32_t* Ku = (const uint32_t*)Ks;
    const uint32_t* Vu = (const uint32_t*)Vs;

    long base = (long)blockIdx.y * CN * CDH;
    const float* Qg = Q + base + (long)blockIdx.x * 128 * CDH;
    const float* Kg = Kg_ + base;
    const float* Vg = Vg_ + base;
    float* Og = O + base + (long)blockIdx.x * 128 * CDH;

    int tid = threadIdx.x, warp = tid >> 5, lane = tid & 31;
    int g = lane >> 2, tg = lane & 3;
    int r0 = warp * 16;

    #pragma unroll
    for (int i = 0; i < 8; i++) {
        int f = tid + i * 256;
        int r = f >> 4, c4 = (f & 15) * 4;
        cpasync16(Qs_b + (uint32_t)((r * SK + c4) * 4), Qg + r * CDH + c4);
    }
    cpcommit();

    auto load_kv = [&](int t, int s) {
        const float* Kt = Kg + t * KT * CDH;
        const float* Vt = Vg + t * KT * CDH;
        #pragma unroll
        for (int i = 0; i < 4; i++) {
            int f = tid + i * 256;
            int r = f >> 4, c4 = (f & 15) * 4;
            cpasync16(Ks_b + (uint32_t)(((s * KT + r) * SK + c4) * 4), Kt + r * CDH + c4);
            cpasync16(Vs_b + (uint32_t)(((s * KT + r) * SV + c4) * 4), Vt + r * CDH + c4);
        }
        cpcommit();
    };
    load_kv(0, 0);

    cpwait1();            // Q done
    __syncthreads();

    uint32_t aq[8][4];
    #pragma unroll
    for (int kf = 0; kf < 8; kf++) {
        aq[kf][0] = f2tf(Qs[(r0 + g)     * SK + kf * 8 + tg]);
        aq[kf][1] = f2tf(Qs[(r0 + g + 8) * SK + kf * 8 + tg]);
        aq[kf][2] = f2tf(Qs[(r0 + g)     * SK + kf * 8 + tg + 4]);
        aq[kf][3] = f2tf(Qs[(r0 + g + 8) * SK + kf * 8 + tg + 4]);
    }

    float m0 = -3.4e38f, m1 = -3.4e38f, l0 = 0.f, l1 = 0.f;
    float o[8][4];
    #pragma unroll
    for (int nf = 0; nf < 8; nf++)
        #pragma unroll
        for (int q = 0; q < 4; q++) o[nf][q] = 0.f;

    for (int t = 0; t < 16; t++) {
        int s = t & 1;
        if (t < 15) load_kv(t + 1, s ^ 1);
        if (t < 15) cpwait1(); else cpwait0();
        __syncthreads();
        // fp32 -> tf32 in place for stage s
        #pragma unroll
        for (int i = 0; i < 4; i++) {
            int f = tid + i * 256;
            int r = f >> 4, c4 = (f & 15) * 4;
            float4* kp = (float4*)&Ks[(s * KT + r) * SK + c4];
            float4 kv = *kp;
            *(uint4*)kp = make_uint4(f2tf(kv.x), f2tf(kv.y), f2tf(kv.z), f2tf(kv.w));
            float4* vp = (float4*)&Vs[(s * KT + r) * SV + c4];
            float4 vv = *vp;
            *(uint4*)vp = make_uint4(f2tf(vv.x), f2tf(vv.y), f2tf(vv.z), f2tf(vv.w));
        }
        __syncthreads();

        // S = Q @ K^T  (per-warp [16,64])
        float sc[8][4];
        #pragma unroll
        for (int nf = 0; nf < 8; nf++)
            #pragma unroll
            for (int q = 0; q < 4; q++) sc[nf][q] = 0.f;
        #pragma unroll
        for (int kf = 0; kf < 8; kf++) {
            #pragma unroll
            for (int nf = 0; nf < 8; nf++) {
                uint32_t b[2];
                b[0] = Ku[(s * KT + nf * 8 + g) * SK + kf * 8 + tg];
                b[1] = Ku[(s * KT + nf * 8 + g) * SK + kf * 8 + tg + 4];
                mma_tf32(sc[nf], aq[kf], b);
            }
        }

        // online softmax (scale 1/8)
        float mx0 = -3.4e38f, mx1 = -3.4e38f;
        #pragma unroll
        for (int nf = 0; nf < 8; nf++) {
            mx0 = fmaxf(mx0, fmaxf(sc[nf][0], sc[nf][1]));
            mx1 = fmaxf(mx1, fmaxf(sc[nf][2], sc[nf][3]));
        }
        #pragma unroll
        for (int off = 1; off <= 2; off <<= 1) {
            mx0 = fmaxf(mx0, __shfl_xor_sync(0xffffffffu, mx0, off));
            mx1 = fmaxf(mx1, __shfl_xor_sync(0xffffffffu, mx1, off));
        }
        float mn0 = fmaxf(m0, mx0 * 0.125f);
        float mn1 = fmaxf(m1, mx1 * 0.125f);
        float cr0 = __expf(m0 - mn0);
        float cr1 = __expf(m1 - mn1);
        l0 *= cr0; l1 *= cr1;
        #pragma unroll
        for (int nf = 0; nf < 8; nf++) {
            o[nf][0] *= cr0; o[nf][1] *= cr0;
            o[nf][2] *= cr1; o[nf][3] *= cr1;
        }
        float rs0 = 0.f, rs1 = 0.f;
        #pragma unroll
        for (int nf = 0; nf < 8; nf++) {
            float p0 = __expf(sc[nf][0] * 0.125f - mn0);
            float p1 = __expf(sc[nf][1] * 0.125f - mn0);
            float p2 = __expf(sc[nf][2] * 0.125f - mn1);
            float p3 = __expf(sc[nf][3] * 0.125f - mn1);
            rs0 += p0 + p1;  rs1 += p2 + p3;
            sc[nf][0] = __uint_as_float(f2tf(p0));
            sc[nf][1] = __uint_as_float(f2tf(p1));
            sc[nf][2] = __uint_as_float(f2tf(p2));
            sc[nf][3] = __uint_as_float(f2tf(p3));
        }
        #pragma unroll
        for (int off = 1; off <= 2; off <<= 1) {
            rs0 += __shfl_xor_sync(0xffffffffu, rs0, off);
            rs1 += __shfl_xor_sync(0xffffffffu, rs1, off);
        }
        l0 += rs0; l1 += rs1; m0 = mn0; m1 = mn1;

        // O += P @ V : gather A-frags of P via intra-quad shuffles
        int srcA = (g << 2) + (tg >> 1);
        int srcB = srcA + 2;
        bool odd = tg & 1;
        #pragma unroll
        for (int kf = 0; kf < 8; kf++) {
            float u0 = __shfl_sync(0xffffffffu, sc[kf][0], srcA);
            float u1 = __shfl_sync(0xffffffffu, sc[kf][1], srcA);
            float u2 = __shfl_sync(0xffffffffu, sc[kf][2], srcA);
            float u3 = __shfl_sync(0xffffffffu, sc[kf][3], srcA);
            float w0 = __shfl_sync(0xffffffffu, sc[kf][0], srcB);
            float w1 = __shfl_sync(0xffffffffu, sc[kf][1], srcB);
            float w2 = __shfl_sync(0xffffffffu, sc[kf][2], srcB);
            float w3 = __shfl_sync(0xffffffffu, sc[kf][3], srcB);
            uint32_t a[4];
            a[0] = __float_as_uint(odd ? u1 : u0);
            a[1] = __float_as_uint(odd ? u3 : u2);
            a[2] = __float_as_uint(odd ? w1 : w0);
            a[3] = __float_as_uint(odd ? w3 : w2);
            #pragma unroll
            for (int nf = 0; nf < 8; nf++) {
                uint32_t b[2];
                b[0] = Vu[(s * KT + kf * 8 + tg)     * SV + nf * 8 + g];
                b[1] = Vu[(s * KT + kf * 8 + tg + 4) * SV + nf * 8 + g];
                mma_tf32(o[nf], a, b);
            }
        }
        __syncthreads();
    }

    float inv0 = 1.f / l0, inv1 = 1.f / l1;
    #pragma unroll
    for (int nf = 0; nf < 8; nf++) {
        int c = nf * 8 + tg * 2;
        *(float2*)(Og + (long)(r0 + g)     * CDH + c) = make_float2(o[nf][0] * inv0, o[nf][1] * inv0);
        *(float2*)(Og + (long)(r0 + g + 8) * CDH + c) = make_float2(o[nf][2] * inv1, o[nf][3] * inv1);
    }
}
constexpr int SM_FLASH = (128 * 68 + 2 * 64 * 68 + 2 * 64 * 72) * 4;  // 106496

// ---------------- fp32 tiled SGEMM (fc2 only) ----------------
template<int ACT>
__global__ void sgemm(const float* __restrict__ A, const float* __restrict__ Bm,
                      const float* __restrict__ bias, float* __restrict__ C,
                      int M, int N, int K)
{
    __shared__ float As[16][68];
    __shared__ float Bs[16][68];
    int tx = threadIdx.x;
    int tr = tx >> 4, tc = tx & 15;
    int row0 = blockIdx.y * 64, col0 = blockIdx.x * 64;

    float acc[4][4] = {};
    for (int k0 = 0; k0 < K; k0 += 16) {
        #pragma unroll
        for (int i = 0; i < 4; i++) {
            int idx = tx * 4 + i;
            int m = idx >> 4, k = idx & 15;
            int gr = row0 + m;
            As[k][m] = (gr < M) ? A[(long)gr * K + k0 + k] : 0.f;
        }
        #pragma unroll
        for (int i = 0; i < 4; i++) {
            int idx = tx * 4 + i;
            int k = idx >> 6, n = idx & 63;
            int gn = col0 + n;
            Bs[k][n] = (gn < N) ? Bm[(long)(k0 + k) * N + gn] : 0.f;
        }
        __syncthreads();
        #pragma unroll
        for (int k = 0; k < 16; k++) {
            float a[4], b[4];
            #pragma unroll
            for (int i = 0; i < 4; i++) a[i] = As[k][tr * 4 + i];
            #pragma unroll
            for (int j = 0; j < 4; j++) b[j] = Bs[k][tc * 4 + j];
            #pragma unroll
            for (int i = 0; i < 4; i++)
                #pragma unroll
                for (int j = 0; j < 4; j++)
                    acc[i][j] = fmaf(a[i], b[j], acc[i][j]);
        }
        __syncthreads();
    }
    #pragma unroll
    for (int i = 0; i < 4; i++) {
        int gr = row0 + tr * 4 + i;
        if (gr >= M) continue;
        #pragma unroll
        for (int j = 0; j < 4; j++) {
            int gn = col0 + tc * 4 + j;
            if (gn >= N) continue;
            float v = acc[i][j];
            if (bias) v += bias[gn];
            if (ACT == 1) v = v > 0.f ? v : 0.f;
            C[(long)gr * N + gn] = v;
        }
    }
}

// ---------------- logits: warp per row, N=7 ----------------
__global__ void logits_kernel(const float* __restrict__ H, const float* __restrict__ W,
                              const float* __restrict__ bb, float* __restrict__ out)
{
    int warp = threadIdx.x >> 5, lane = threadIdx.x & 31;
    int row = blockIdx.x * 8 + warp;
    float hv[8];
    #pragma unroll
    for (int j = 0; j < 8; j++) hv[j] = H[(long)row * CHID + j * 32 + lane];
    float acc[CNC];
    #pragma unroll
    for (int c = 0; c < CNC; c++) {
        float a = 0.f;
        #pragma unroll
        for (int j = 0; j < 8; j++) a = fmaf(hv[j], W[(j * 32 + lane) * CNC + c], a);
        acc[c] = a;
    }
    #pragma unroll
    for (int c = 0; c < CNC; c++)
        #pragma unroll
        for (int off = 16; off > 0; off >>= 1)
            acc[c] += __shfl_xor_sync(0xffffffffu, acc[c], off);
    if (lane < CNC) out[(long)row * CNC + lane] = acc[lane] + bb[lane];
}

// ---------------- P_l_1 ----------------
__global__ void pl1_kernel(const float* __restrict__ sadj, const float* __restrict__ P,
                           float* __restrict__ out)
{
    long idx = (long)blockIdx.x * 256 + threadIdx.x;
    int d = idx & (CHID - 1);
    int n = (idx >> 8) & (CN - 1);
    int b = (int)(idx >> 18);
    const float* sa = sadj + (long)b * CM * CN + n;
    const float* Pb = P + (long)b * CM * CHID + d;
    float acc = 0.f;
    #pragma unroll
    for (int m = 0; m < CM; m++) acc = fmaf(sa[m * CN], Pb[m * CHID], acc);
    out[idx] = acc;
}

// ---------------- P_agg ----------------
__global__ void pagg_kernel(const float* __restrict__ sadj, const float* __restrict__ H,
                            float* __restrict__ out)
{
    int bm = blockIdx.x;
    int b = bm >> 3;
    int d = threadIdx.x;
    const float* sa = sadj + (long)bm * CN;
    const float* Hb = H + (long)b * CN * CHID + d;
    float acc = 0.f;
    #pragma unroll 4
    for (int n = 0; n < CN; n++) acc = fmaf(sa[n], Hb[(long)n * CHID], acc);
    out[(long)bm * CHID + d] = acc;
}

// ---------------- e1/e2 dots ----------------
__global__ void dots_kernel(const float* __restrict__ h, const float* __restrict__ a1,
                            const float* __restrict__ a2,
                            float* __restrict__ e1, float* __restrict__ e2)
{
    __shared__ float s1[256], s2[256];
    int row = blockIdx.x, t = threadIdx.x;
    float v = h[(long)row * CHID + t];
    s1[t] = v * a1[t];
    s2[t] = v * a2[t];
    __syncthreads();
    for (int o = 128; o > 0; o >>= 1) {
        if (t < o) { s1[t] += s1[t + o]; s2[t] += s2[t + o]; }
        __syncthreads();
    }
    if (t == 0) { e1[row] = s1[0]; e2[row] = s2[0]; }
}

// ---------------- rel_sc ----------------
__global__ void relsc_kernel(const float* __restrict__ rel, const float* __restrict__ a3,
                             float* __restrict__ out)
{
    __shared__ float s[256];
    int r = blockIdx.x, t = threadIdx.x;
    s[t] = rel[r * CHID + t] * a3[t];
    __syncthreads();
    for (int o = 128; o > 0; o >>= 1) {
        if (t < o) s[t] += s[t + o];
        __syncthreads();
    }
    if (t == 0) out[r] = s[0];
}

// ---------------- GAT edge scores + masked softmax (vectorized) ----------------
__global__ void gat_att_kernel(const float* __restrict__ e1, const float* __restrict__ e2,
                               const float* __restrict__ rsc,
                               const int* __restrict__ adj, const int* __restrict__ smask,
                               float* __restrict__ att)
{
    __shared__ float red[256];
    int bi = blockIdx.x;
    int b = bi >> 10;
    long base = (long)bi * CN;
    int t = threadIdx.x;
    float E1 = e1[bi];
    float r0 = rsc[0], r1 = rsc[1];

    int4   ad = ((const int4*)(adj + base))[t];
    int4   sk = ((const int4*)(smask + base))[t];
    float4 ev = ((const float4*)(e2 + (long)b * CN))[t];

    float vals[4];
    {
        float e;
        e = E1 + ev.x + (sk.x ? r1 : r0); e = e >= 0.f ? e : ALPHAF * e; vals[0] = ad.x ? e : NEGF;
        e = E1 + ev.y + (sk.y ? r1 : r0); e = e >= 0.f ? e : ALPHAF * e; vals[1] = ad.y ? e : NEGF;
        e = E1 + ev.z + (sk.z ? r1 : r0); e = e >= 0.f ? e : ALPHAF * e; vals[2] = ad.z ? e : NEGF;
        e = E1 + ev.w + (sk.w ? r1 : r0); e = e >= 0.f ? e : ALPHAF * e; vals[3] = ad.w ? e : NEGF;
    }
    float mx = fmaxf(fmaxf(vals[0], vals[1]), fmaxf(vals[2], vals[3]));
    red[t] = mx; __syncthreads();
    for (int o = 128; o > 0; o >>= 1) {
        if (t < o) red[t] = fmaxf(red[t], red[t + o]);
        __syncthreads();
    }
    mx = red[0]; __syncthreads();
    float s = 0.f;
    #pragma unroll
    for (int q = 0; q < 4; q++) { vals[q] = expf(vals[q] - mx); s += vals[q]; }
    red[t] = s; __syncthreads();
    for (int o = 128; o > 0; o >>= 1) {
        if (t < o) red[t] += red[t + o];
        __syncthreads();
    }
    float inv = 1.f / red[0];
    ((float4*)(att + base))[t] =
        make_float4(vals[0] * inv, vals[1] * inv, vals[2] * inv, vals[3] * inv);
}

// ---------------- LayerNorm ----------------
__global__ void ln_kernel(const float* __restrict__ T, const float* __restrict__ Hold,
                          const float* __restrict__ g, const float* __restrict__ bb,
                          float* __restrict__ out)
{
    __shared__ float red[256];
    int row = blockIdx.x, t = threadIdx.x;
    long off = (long)row * CHID + t;
    float v = T[off] + Hold[off];
    red[t] = v; __syncthreads();
    for (int o = 128; o > 0; o >>= 1) {
        if (t < o) red[t] += red[t + o];
        __syncthreads();
    }
    float mu = red[0] * (1.f / CHID);
    __syncthreads();
    float dv = v - mu;
    red[t] = dv * dv; __syncthreads();
    for (int o = 128; o > 0; o >>= 1) {
        if (t < o) red[t] += red[t + o];
        __syncthreads();
    }
    float var = red[0] * (1.f / CHID);
    out[off] = dv * rsqrtf(var + 1e-5f) * g[t] + bb[t];
}

// ---------------- GRU3d ----------------
__global__ void gru_kernel(float* __restrict__ P, const float* __restrict__ Pagg,
                           const float* __restrict__ wz, const float* __restrict__ uz,
                           const float* __restrict__ wr, const float* __restrict__ ur,
                           const float* __restrict__ w,  const float* __restrict__ u)
{
    __shared__ float sp[CHID], sq[CHID];
    int r = blockIdx.x;
    int c = threadIdx.x;
    sp[c] = P[(long)r * CHID + c];
    sq[c] = Pagg[(long)r * CHID + c];
    __syncthreads();
    float az = 0, bz = 0, ar = 0, br = 0, aw = 0, bw = 0;
    for (int k = 0; k < CHID; k++) {
        float pk = sp[k], qk = sq[k];
        az = fmaf(pk, wz[k * CHID + c], az); bz = fmaf(qk, uz[k * CHID + c], bz);
        ar = fmaf(pk, wr[k * CHID + c], ar); br = fmaf(qk, ur[k * CHID + c], br);
        aw = fmaf(pk, w [k * CHID + c], aw); bw = fmaf(qk, u [k * CHID + c], bw);
    }
    float z  = 1.f / (1.f + expf(-(az + bz)));
    float rr = 1.f / (1.f + expf(-(ar + br)));
    float hh = tanhf(aw + rr * bw);
    P[(long)r * CHID + c] = (1.f - z) * sp[c] + z * hh;
}

// ---------------- p_sim ----------------
__global__ void psim_kernel(const float* __restrict__ P, float* __restrict__ outp, int tail)
{
    __shared__ float red[64];
    int t = threadIdx.x;
    int b = t >> 3, m = t & 7;
    const float* Pb = P + (long)b * CM * CHID;
    float s = 0.f;
    for (int k2 = 0; k2 < CM; k2++) {
        if (k2 == m) continue;
        float d = 0.f;
        for (int dd = 0; dd < CHID; dd++)
            d = fmaf(Pb[m * CHID + dd], Pb[k2 * CHID + dd], d);
        s += d;
    }
    red[t] = s; __syncthreads();
    if ((t & 7) < 4) red[t] += red[t + 4]; __syncthreads();
    if ((t & 7) < 2) red[t] += red[t + 2]; __syncthreads();
    if ((t & 7) < 1) red[t] += red[t + 1]; __syncthreads();
    if (tail >= CB) {
        if (t < CB) outp[t] = red[t * 8] / (float)(CM * CM);
    } else {
        if (t == 0) {
            float tot = 0.f;
            for (int b2 = 0; b2 < CB; b2++) tot += red[b2 * 8];
            outp[0] = tot / (float)(CB * CM * CM);
        }
    }
}

// ---------------- host orchestration ----------------
extern "C" void kernel_launch(void* const* d_in, const int* in_sizes, int n_in,
                              void* d_out, int out_size)
{
    const float* x     = (const float*)d_in[0];
    const int*   adj   = (const int*)  d_in[1];
    const int*   smask = (const int*)  d_in[2];
    const float* sf    = (const float*)d_in[3];
    const float* sadj  = (const float*)d_in[4];
    const float* fc1w  = (const float*)d_in[6];
    const float* fc1b  = (const float*)d_in[7];
    const float* fc2w  = (const float*)d_in[8];
    const float* fc2b  = (const float*)d_in[9];
    const float* gatW  = (const float*)d_in[10];
    const float* gata  = (const float*)d_in[11];
    const float* rel   = (const float*)d_in[12];
    const float* gwz   = (const float*)d_in[13];
    const float* guz   = (const float*)d_in[14];
    const float* gwr   = (const float*)d_in[15];
    const float* gur   = (const float*)d_in[16];
    const float* gw    = (const float*)d_in[17];
    const float* gu    = (const float*)d_in[18];
    const float* wv    = (const float*)d_in[19];
    const float* bv    = (const float*)d_in[20];
    const float* wk    = (const float*)d_in[21];
    const float* bk    = (const float*)d_in[22];
    const float* wq    = (const float*)d_in[23];
    const float* bq    = (const float*)d_in[24];
    const float* wo    = (const float*)d_in[25];
    const float* bo    = (const float*)d_in[26];
    const float* lng   = (const float*)d_in[27];
    const float* lnb   = (const float*)d_in[28];
    const float* outw  = (const float*)d_in[29];
    const float* outb  = (const float*)d_in[30];
    float* out = (float*)d_out;

    float *H, *Hn, *P, *Pagg, *Pl1, *hb, *Agg, *Qb, *Kb, *Vb, *ctx, *Tb, *att, *e1, *e2, *rsc;
    cudaGetSymbolAddress((void**)&H,    g_H);
    cudaGetSymbolAddress((void**)&Hn,   g_Hn);
    cudaGetSymbolAddress((void**)&P,    g_P);
    cudaGetSymbolAddress((void**)&Pagg, g_Pagg);
    cudaGetSymbolAddress((void**)&Pl1,  g_Pl1);
    cudaGetSymbolAddress((void**)&hb,   g_h);
    cudaGetSymbolAddress((void**)&Agg,  g_Agg);
    cudaGetSymbolAddress((void**)&Qb,   g_Q);
    cudaGetSymbolAddress((void**)&Kb,   g_K);
    cudaGetSymbolAddress((void**)&Vb,   g_V);
    cudaGetSymbolAddress((void**)&ctx,  g_ctx);
    cudaGetSymbolAddress((void**)&Tb,   g_T);
    cudaGetSymbolAddress((void**)&att,  g_att);
    cudaGetSymbolAddress((void**)&e1,   g_e1);
    cudaGetSymbolAddress((void**)&e2,   g_e2);
    cudaGetSymbolAddress((void**)&rsc,  g_rsc);

    cudaFuncSetAttribute(tgemm<0>, cudaFuncAttributeMaxDynamicSharedMemorySize, SM_TG);
    cudaFuncSetAttribute(tgemm<1>, cudaFuncAttributeMaxDynamicSharedMemorySize, SM_TG);
    cudaFuncSetAttribute(tgemm<2>, cudaFuncAttributeMaxDynamicSharedMemorySize, SM_TG);
    cudaFuncSetAttribute(tgemm_pair, cudaFuncAttributeMaxDynamicSharedMemorySize, SM_TG);
    cudaFuncSetAttribute(flash_kernel, cudaFuncAttributeMaxDynamicSharedMemorySize, SM_FLASH);

    dim3 blk(256);
    const int BN = CB * CN;                          // 8192
    const long HH = (long)CHID * CHID;               // 65536

    // H = relu(x @ fc1_w + b)
    tgemm<1><<<dim3(2, 64, 1), blk, SM_TG>>>(x, fc1w, fc1b, H, BN, CHID, CDIN, 0, 0, 0, 1.f);
    // P = relu(s_feature @ fc2_w + b)
    sgemm<1><<<dim3(4, 1, 1), blk>>>(sf, fc2w, fc2b, P, CB * CM, CHID, CDIN);

    for (int l = 0; l < CL; l++) {
        float* cur = l ? Hn : H;
        float* nxt = l ? H : Hn;

        // P_l_1 = s_adj^T @ P
        pl1_kernel<<<BN * CHID / 256, blk>>>(sadj, P, Pl1);

        // paired: h = cur @ gat_W[l] ; V = cur @ wv + bv
        {
            G2 a;
            a.A[0] = cur;           a.A[1] = cur;
            a.B[0] = gatW + l * HH; a.B[1] = wv + l * HH;
            a.bias[0] = nullptr;    a.bias[1] = bv + l * CHID;
            a.C[0] = hb;            a.C[1] = Vb;
            tgemm_pair<<<dim3(2, 64, 2), blk, SM_TG>>>(a, BN, CHID, CHID);
        }
        // edge-score ingredients
        dots_kernel<<<BN, blk>>>(hb, gata + l * 3 * CHID, gata + l * 3 * CHID + CHID, e1, e2);
        relsc_kernel<<<2, blk>>>(rel + l * 2 * CHID, gata + l * 3 * CHID + 2 * CHID, rsc);
        gat_att_kernel<<<BN, blk>>>(e1, e2, rsc, adj, smask, att);
        // Agg = elu(att @ h)
        tgemm<2><<<dim3(2, 8, CB), blk, SM_TG>>>(att, hb, nullptr, Agg,
                                                 CN, CHID, CN,
                                                 (long)CN * CN, (long)CN * CHID, (long)CN * CHID, 1.f);
        // paired: K = Pl1 @ wk + bk ; Q = Agg @ wq + bq
        {
            G2 a;
            a.A[0] = Pl1;           a.A[1] = Agg;
            a.B[0] = wk + l * HH;   a.B[1] = wq + l * HH;
            a.bias[0] = bk + l * CHID; a.bias[1] = bq + l * CHID;
            a.C[0] = Kb;            a.C[1] = Qb;
            tgemm_pair<<<dim3(2, 64, 2), blk, SM_TG>>>(a, BN, CHID, CHID);
        }
        // fused MHA
        flash_kernel<<<dim3(8, 32), blk, SM_FLASH>>>(Qb, Kb, Vb, ctx);
        // T = ctx @ wo + bo ;  H_new = LN(T + H)
        tgemm<0><<<dim3(2, 64, 1), blk, SM_TG>>>(ctx, wo + l * HH, bo + l * CHID, Tb,
                                                 BN, CHID, CHID, 0, 0, 0, 1.f);
        ln_kernel<<<BN, blk>>>(Tb, cur, lng + l * CHID, lnb + l * CHID, nxt);

        // GRU speaker update (uses pre-update H)
        pagg_kernel<<<CB * CM, blk>>>(sadj, cur, Pagg);
        gru_kernel<<<CB * CM, blk>>>(P, Pagg,
                                     gwz + l * HH, guz + l * HH,
                                     gwr + l * HH, gur + l * HH,
                                     gw + l * HH,  gu + l * HH);
    }

    // logits
    logits_kernel<<<BN / 8, blk>>>(H, outw, outb, out);
    // p_sim
    psim_kernel<<<1, 64>>>(P, out + (long)BN * CNC, out_size - BN * CNC);
}

// round 6
// speedup vs baseline: 2.5335x; 1.0759x over previous
#include <cuda_runtime.h>
#include <math.h>
#include <stdint.h>

// ---------------- problem constants ----------------
constexpr int CB   = 8;      // batch
constexpr int CN   = 1024;   // nodes
constexpr int CM   = 8;      // speakers
constexpr int CDIN = 1024;
constexpr int CHID = 256;
constexpr int CL   = 2;
constexpr int CNC  = 7;
constexpr int CNH  = 4;
constexpr int CDH  = 64;
#define NEGF  (-9e15f)
#define ALPHAF 0.1f

// ---------------- scratch ----------------
__device__ float g_H   [CB*CN*CHID];
__device__ float g_Hn  [CB*CN*CHID];
__device__ float g_P   [CB*CM*CHID];
__device__ float g_Pagg[CB*CM*CHID];
__device__ float g_Pl1 [CB*CN*CHID];
__device__ float g_h   [CB*CN*CHID];
__device__ float g_Agg [CB*CN*CHID];
__device__ float g_Q   [CB*CN*CHID];
__device__ float g_K   [CB*CN*CHID];
__device__ float g_V   [CB*CN*CHID];
__device__ float g_ctx [CB*CN*CHID];
__device__ float g_T   [CB*CN*CHID];
__device__ float g_att [(long)CB*CN*CN];
__device__ float g_e1  [CB*CN];
__device__ float g_e2  [CB*CN];
__device__ float g_rsc [2];

// ---------------- tf32 / async helpers ----------------
__device__ __forceinline__ uint32_t f2tf(float f) {
    uint32_t u;
    asm("cvt.rna.tf32.f32 %0, %1;" : "=r"(u) : "f"(f));
    return u;
}
__device__ __forceinline__ void mma_tf32(float c[4], const uint32_t a[4], const uint32_t b[2]) {
    asm volatile(
        "mma.sync.aligned.m16n8k8.row.col.f32.tf32.tf32.f32 "
        "{%0,%1,%2,%3}, {%4,%5,%6,%7}, {%8,%9}, {%0,%1,%2,%3};\n"
        : "+f"(c[0]), "+f"(c[1]), "+f"(c[2]), "+f"(c[3])
        : "r"(a[0]), "r"(a[1]), "r"(a[2]), "r"(a[3]), "r"(b[0]), "r"(b[1]));
}
__device__ __forceinline__ void cpasync16(uint32_t saddr, const void* gptr) {
    asm volatile("cp.async.cg.shared.global [%0], [%1], 16;\n" :: "r"(saddr), "l"(gptr));
}
__device__ __forceinline__ void cpcommit() { asm volatile("cp.async.commit_group;\n"); }
__device__ __forceinline__ void cpwait0()  { asm volatile("cp.async.wait_group 0;\n"); }
__device__ __forceinline__ void cpwait1()  { asm volatile("cp.async.wait_group 1;\n"); }

// ================= core GEMM tile (128x128, KS=32, 2-stage, 2 CTAs/SM) =================
struct TileCtx {
    float *As, *Bs;
    uint32_t As_b, Bs_b;
    const float *Ag, *Bg;
    int K, N;
    int tid;
};
constexpr int T_strA = 36, T_strB = 132;
constexpr int T_AW = 128 * T_strA, T_BW = 32 * T_strB;
constexpr int SM_TG = (2 * (T_AW + T_BW)) * 4;   // 70656 bytes

__device__ __forceinline__ void tg_load_stage(TileCtx& c, int kt, int s) {
    int k0 = kt * 32;
    #pragma unroll
    for (int i = 0; i < 4; i++) {
        int f = c.tid + i * 256;
        int m = f >> 3, k4 = (f & 7) * 4;
        cpasync16(c.As_b + (uint32_t)(((s * 128 + m) * T_strA + k4) * 4),
                  c.Ag + (long)m * c.K + k0 + k4);
    }
    #pragma unroll
    for (int i = 0; i < 4; i++) {
        int f = c.tid + i * 256;
        int k = f >> 5, n4 = (f & 31) * 4;
        cpasync16(c.Bs_b + (uint32_t)(((s * 32 + k) * T_strB + n4) * 4),
                  c.Bg + (long)(k0 + k) * c.N + n4);
    }
    cpcommit();
}

template<int ACT>
__device__ __forceinline__ void tg_body(
    TileCtx& c, const float* bias, float* C, int M, int N, int K,
    int row0, int col0, float scale)
{
    int tid  = c.tid;
    int warp = tid >> 5, lane = tid & 31;
    int g = lane >> 2, tg = lane & 3;
    int mw = warp >> 2, nw = warp & 3;

    float acc[4][4][4];
    #pragma unroll
    for (int mi = 0; mi < 4; mi++)
        #pragma unroll
        for (int ni = 0; ni < 4; ni++)
            #pragma unroll
            for (int q = 0; q < 4; q++) acc[mi][ni][q] = 0.f;

    int nk = K / 32;
    tg_load_stage(c, 0, 0);

    for (int kt = 0; kt < nk; kt++) {
        cpwait0();
        __syncthreads();
        int s = kt & 1;
        if (kt + 1 < nk) tg_load_stage(c, kt + 1, s ^ 1);

        const float* Asb = c.As + s * T_AW;
        const float* Bsb = c.Bs + s * T_BW;
        #pragma unroll
        for (int ks = 0; ks < 32; ks += 8) {
            uint32_t a[4][4], b[4][2];
            #pragma unroll
            for (int mi = 0; mi < 4; mi++) {
                int mr = mw * 64 + mi * 16;
                a[mi][0] = f2tf(Asb[(mr + g)     * T_strA + ks + tg]);
                a[mi][1] = f2tf(Asb[(mr + g + 8) * T_strA + ks + tg]);
                a[mi][2] = f2tf(Asb[(mr + g)     * T_strA + ks + tg + 4]);
                a[mi][3] = f2tf(Asb[(mr + g + 8) * T_strA + ks + tg + 4]);
            }
            #pragma unroll
            for (int ni = 0; ni < 4; ni++) {
                int nc = nw * 32 + ni * 8;
                b[ni][0] = f2tf(Bsb[(ks + tg)     * T_strB + nc + g]);
                b[ni][1] = f2tf(Bsb[(ks + tg + 4) * T_strB + nc + g]);
            }
            #pragma unroll
            for (int mi = 0; mi < 4; mi++)
                #pragma unroll
                for (int ni = 0; ni < 4; ni++)
                    mma_tf32(acc[mi][ni], a[mi], b[ni]);
        }
        __syncthreads();
    }

    #pragma unroll
    for (int mi = 0; mi < 4; mi++) {
        #pragma unroll
        for (int ni = 0; ni < 4; ni++) {
            int r = row0 + mw * 64 + mi * 16 + g;
            int cc0 = col0 + nw * 32 + ni * 8 + tg * 2;
            float b0 = bias ? bias[cc0] : 0.f;
            float b1 = bias ? bias[cc0 + 1] : 0.f;
            #pragma unroll
            for (int rr = 0; rr < 2; rr++) {
                float v0 = acc[mi][ni][rr * 2 + 0] * scale + b0;
                float v1 = acc[mi][ni][rr * 2 + 1] * scale + b1;
                if (ACT == 1) { v0 = fmaxf(v0, 0.f); v1 = fmaxf(v1, 0.f); }
                else if (ACT == 2) {
                    v0 = v0 > 0.f ? v0 : expm1f(v0);
                    v1 = v1 > 0.f ? v1 : expm1f(v1);
                }
                *(float2*)(C + (long)(r + rr * 8) * N + cc0) = make_float2(v0, v1);
            }
        }
    }
}

// ---------------- single GEMM (batched via strides) ----------------
template<int ACT>
__global__ void __launch_bounds__(256, 2) tgemm(
    const float* __restrict__ A, const float* __restrict__ Bm,
    const float* __restrict__ bias, float* __restrict__ C,
    int M, int N, int K, long sA, long sB, long sC, float scale)
{
    extern __shared__ float smem[];
    int bz = blockIdx.z;
    TileCtx c;
    c.As = smem; c.Bs = smem + 2 * T_AW;
    c.As_b = (uint32_t)__cvta_generic_to_shared(c.As);
    c.Bs_b = (uint32_t)__cvta_generic_to_shared(c.Bs);
    c.K = K; c.N = N; c.tid = threadIdx.x;
    int row0 = blockIdx.y * 128, col0 = blockIdx.x * 128;
    const float* Ab = A + (long)bz * sA;
    const float* Bb = Bm + (long)bz * sB;
    c.Ag = Ab + (long)row0 * K;
    c.Bg = Bb + col0;
    tg_body<ACT>(c, bias, C + (long)bz * sC, M, N, K, row0, col0, scale);
}

// ---------------- paired GEMM: z selects {A,B,bias,C} ----------------
struct G2 { const float* A[2]; const float* B[2]; const float* bias[2]; float* C[2]; };
__global__ void __launch_bounds__(256, 2) tgemm_pair(G2 args, int M, int N, int K)
{
    extern __shared__ float smem[];
    int z = blockIdx.z;
    TileCtx c;
    c.As = smem; c.Bs = smem + 2 * T_AW;
    c.As_b = (uint32_t)__cvta_generic_to_shared(c.As);
    c.Bs_b = (uint32_t)__cvta_generic_to_shared(c.Bs);
    c.K = K; c.N = N; c.tid = threadIdx.x;
    int row0 = blockIdx.y * 128, col0 = blockIdx.x * 128;
    c.Ag = args.A[z] + (long)row0 * K;
    c.Bg = args.B[z] + col0;
    tg_body<0>(c, args.bias[z], args.C[z], M, N, K, row0, col0, 1.f);
}

// ---------------- fused flash attention, 64-row KV tiles ----------------
__global__ void __launch_bounds__(256, 2) flash_kernel(
    const float* __restrict__ Q, const float* __restrict__ Kg_,
    const float* __restrict__ Vg_, float* __restrict__ O)
{
    constexpr int SK = 68, SV = 72, KT = 64;
    extern __shared__ float sm[];
    float* Qs = sm;                          // 128*68
    float* Ks = sm + 128 * SK;               // 2 * 64*68
    float* Vs = Ks + 2 * KT * SK;            // 2 * 64*72
    uint32_t Qs_b = (uint32_t)__cvta_generic_to_shared(Qs);
    uint32_t Ks_b = (uint32_t)__cvta_generic_to_shared(Ks);
    uint32_t Vs_b = (uint32_t)__cvta_generic_to_shared(Vs);
    const uint32_t* Ku = (const uint32_t*)Ks;
    const uint32_t* Vu = (const uint32_t*)Vs;

    long base = (long)blockIdx.y * CN * CDH;
    const float* Qg = Q + base + (long)blockIdx.x * 128 * CDH;
    const float* Kg = Kg_ + base;
    const float* Vg = Vg_ + base;
    float* Og = O + base + (long)blockIdx.x * 128 * CDH;

    int tid = threadIdx.x, warp = tid >> 5, lane = tid & 31;
    int g = lane >> 2, tg = lane & 3;
    int r0 = warp * 16;

    #pragma unroll
    for (int i = 0; i < 8; i++) {
        int f = tid + i * 256;
        int r = f >> 4, c4 = (f & 15) * 4;
        cpasync16(Qs_b + (uint32_t)((r * SK + c4) * 4), Qg + r * CDH + c4);
    }
    cpcommit();

    auto load_kv = [&](int t, int s) {
        const float* Kt = Kg + t * KT * CDH;
        const float* Vt = Vg + t * KT * CDH;
        #pragma unroll
        for (int i = 0; i < 4; i++) {
            int f = tid + i * 256;
            int r = f >> 4, c4 = (f & 15) * 4;
            cpasync16(Ks_b + (uint32_t)(((s * KT + r) * SK + c4) * 4), Kt + r * CDH + c4);
            cpasync16(Vs_b + (uint32_t)(((s * KT + r) * SV + c4) * 4), Vt + r * CDH + c4);
        }
        cpcommit();
    };
    load_kv(0, 0);

    cpwait1();            // Q done
    __syncthreads();

    uint32_t aq[8][4];
    #pragma unroll
    for (int kf = 0; kf < 8; kf++) {
        aq[kf][0] = f2tf(Qs[(r0 + g)     * SK + kf * 8 + tg]);
        aq[kf][1] = f2tf(Qs[(r0 + g + 8) * SK + kf * 8 + tg]);
        aq[kf][2] = f2tf(Qs[(r0 + g)     * SK + kf * 8 + tg + 4]);
        aq[kf][3] = f2tf(Qs[(r0 + g + 8) * SK + kf * 8 + tg + 4]);
    }

    float m0 = -3.4e38f, m1 = -3.4e38f, l0 = 0.f, l1 = 0.f;
    float o[8][4];
    #pragma unroll
    for (int nf = 0; nf < 8; nf++)
        #pragma unroll
        for (int q = 0; q < 4; q++) o[nf][q] = 0.f;

    for (int t = 0; t < 16; t++) {
        int s = t & 1;
        if (t < 15) load_kv(t + 1, s ^ 1);
        if (t < 15) cpwait1(); else cpwait0();
        __syncthreads();
        // fp32 -> tf32 in place for stage s
        #pragma unroll
        for (int i = 0; i < 4; i++) {
            int f = tid + i * 256;
            int r = f >> 4, c4 = (f & 15) * 4;
            float4* kp = (float4*)&Ks[(s * KT + r) * SK + c4];
            float4 kv = *kp;
            *(uint4*)kp = make_uint4(f2tf(kv.x), f2tf(kv.y), f2tf(kv.z), f2tf(kv.w));
            float4* vp = (float4*)&Vs[(s * KT + r) * SV + c4];
            float4 vv = *vp;
            *(uint4*)vp = make_uint4(f2tf(vv.x), f2tf(vv.y), f2tf(vv.z), f2tf(vv.w));
        }
        __syncthreads();

        // S = Q @ K^T  (per-warp [16,64])
        float sc[8][4];
        #pragma unroll
        for (int nf = 0; nf < 8; nf++)
            #pragma unroll
            for (int q = 0; q < 4; q++) sc[nf][q] = 0.f;
        #pragma unroll
        for (int kf = 0; kf < 8; kf++) {
            #pragma unroll
            for (int nf = 0; nf < 8; nf++) {
                uint32_t b[2];
                b[0] = Ku[(s * KT + nf * 8 + g) * SK + kf * 8 + tg];
                b[1] = Ku[(s * KT + nf * 8 + g) * SK + kf * 8 + tg + 4];
                mma_tf32(sc[nf], aq[kf], b);
            }
        }

        // online softmax (scale 1/8)
        float mx0 = -3.4e38f, mx1 = -3.4e38f;
        #pragma unroll
        for (int nf = 0; nf < 8; nf++) {
            mx0 = fmaxf(mx0, fmaxf(sc[nf][0], sc[nf][1]));
            mx1 = fmaxf(mx1, fmaxf(sc[nf][2], sc[nf][3]));
        }
        #pragma unroll
        for (int off = 1; off <= 2; off <<= 1) {
            mx0 = fmaxf(mx0, __shfl_xor_sync(0xffffffffu, mx0, off));
            mx1 = fmaxf(mx1, __shfl_xor_sync(0xffffffffu, mx1, off));
        }
        float mn0 = fmaxf(m0, mx0 * 0.125f);
        float mn1 = fmaxf(m1, mx1 * 0.125f);
        float cr0 = __expf(m0 - mn0);
        float cr1 = __expf(m1 - mn1);
        l0 *= cr0; l1 *= cr1;
        #pragma unroll
        for (int nf = 0; nf < 8; nf++) {
            o[nf][0] *= cr0; o[nf][1] *= cr0;
            o[nf][2] *= cr1; o[nf][3] *= cr1;
        }
        float rs0 = 0.f, rs1 = 0.f;
        #pragma unroll
        for (int nf = 0; nf < 8; nf++) {
            float p0 = __expf(sc[nf][0] * 0.125f - mn0);
            float p1 = __expf(sc[nf][1] * 0.125f - mn0);
            float p2 = __expf(sc[nf][2] * 0.125f - mn1);
            float p3 = __expf(sc[nf][3] * 0.125f - mn1);
            rs0 += p0 + p1;  rs1 += p2 + p3;
            sc[nf][0] = __uint_as_float(f2tf(p0));
            sc[nf][1] = __uint_as_float(f2tf(p1));
            sc[nf][2] = __uint_as_float(f2tf(p2));
            sc[nf][3] = __uint_as_float(f2tf(p3));
        }
        #pragma unroll
        for (int off = 1; off <= 2; off <<= 1) {
            rs0 += __shfl_xor_sync(0xffffffffu, rs0, off);
            rs1 += __shfl_xor_sync(0xffffffffu, rs1, off);
        }
        l0 += rs0; l1 += rs1; m0 = mn0; m1 = mn1;

        // O += P @ V : gather A-frags of P via intra-quad shuffles
        int srcA = (g << 2) + (tg >> 1);
        int srcB = srcA + 2;
        bool odd = tg & 1;
        #pragma unroll
        for (int kf = 0; kf < 8; kf++) {
            float u0 = __shfl_sync(0xffffffffu, sc[kf][0], srcA);
            float u1 = __shfl_sync(0xffffffffu, sc[kf][1], srcA);
            float u2 = __shfl_sync(0xffffffffu, sc[kf][2], srcA);
            float u3 = __shfl_sync(0xffffffffu, sc[kf][3], srcA);
            float w0 = __shfl_sync(0xffffffffu, sc[kf][0], srcB);
            float w1 = __shfl_sync(0xffffffffu, sc[kf][1], srcB);
            float w2 = __shfl_sync(0xffffffffu, sc[kf][2], srcB);
            float w3 = __shfl_sync(0xffffffffu, sc[kf][3], srcB);
            uint32_t a[4];
            a[0] = __float_as_uint(odd ? u1 : u0);
            a[1] = __float_as_uint(odd ? u3 : u2);
            a[2] = __float_as_uint(odd ? w1 : w0);
            a[3] = __float_as_uint(odd ? w3 : w2);
            #pragma unroll
            for (int nf = 0; nf < 8; nf++) {
                uint32_t b[2];
                b[0] = Vu[(s * KT + kf * 8 + tg)     * SV + nf * 8 + g];
                b[1] = Vu[(s * KT + kf * 8 + tg + 4) * SV + nf * 8 + g];
                mma_tf32(o[nf], a, b);
            }
        }
        __syncthreads();
    }

    float inv0 = 1.f / l0, inv1 = 1.f / l1;
    #pragma unroll
    for (int nf = 0; nf < 8; nf++) {
        int c = nf * 8 + tg * 2;
        *(float2*)(Og + (long)(r0 + g)     * CDH + c) = make_float2(o[nf][0] * inv0, o[nf][1] * inv0);
        *(float2*)(Og + (long)(r0 + g + 8) * CDH + c) = make_float2(o[nf][2] * inv1, o[nf][3] * inv1);
    }
}
constexpr int SM_FLASH = (128 * 68 + 2 * 64 * 68 + 2 * 64 * 72) * 4;  // 106496

// ---------------- fp32 tiled SGEMM (fc2 only) ----------------
template<int ACT>
__global__ void sgemm(const float* __restrict__ A, const float* __restrict__ Bm,
                      const float* __restrict__ bias, float* __restrict__ C,
                      int M, int N, int K)
{
    __shared__ float As[16][68];
    __shared__ float Bs[16][68];
    int tx = threadIdx.x;
    int tr = tx >> 4, tc = tx & 15;
    int row0 = blockIdx.y * 64, col0 = blockIdx.x * 64;

    float acc[4][4] = {};
    for (int k0 = 0; k0 < K; k0 += 16) {
        #pragma unroll
        for (int i = 0; i < 4; i++) {
            int idx = tx * 4 + i;
            int m = idx >> 4, k = idx & 15;
            int gr = row0 + m;
            As[k][m] = (gr < M) ? A[(long)gr * K + k0 + k] : 0.f;
        }
        #pragma unroll
        for (int i = 0; i < 4; i++) {
            int idx = tx * 4 + i;
            int k = idx >> 6, n = idx & 63;
            int gn = col0 + n;
            Bs[k][n] = (gn < N) ? Bm[(long)(k0 + k) * N + gn] : 0.f;
        }
        __syncthreads();
        #pragma unroll
        for (int k = 0; k < 16; k++) {
            float a[4], b[4];
            #pragma unroll
            for (int i = 0; i < 4; i++) a[i] = As[k][tr * 4 + i];
            #pragma unroll
            for (int j = 0; j < 4; j++) b[j] = Bs[k][tc * 4 + j];
            #pragma unroll
            for (int i = 0; i < 4; i++)
                #pragma unroll
                for (int j = 0; j < 4; j++)
                    acc[i][j] = fmaf(a[i], b[j], acc[i][j]);
        }
        __syncthreads();
    }
    #pragma unroll
    for (int i = 0; i < 4; i++) {
        int gr = row0 + tr * 4 + i;
        if (gr >= M) continue;
        #pragma unroll
        for (int j = 0; j < 4; j++) {
            int gn = col0 + tc * 4 + j;
            if (gn >= N) continue;
            float v = acc[i][j];
            if (bias) v += bias[gn];
            if (ACT == 1) v = v > 0.f ? v : 0.f;
            C[(long)gr * N + gn] = v;
        }
    }
}

// ---------------- logits: warp per row, N=7 ----------------
__global__ void logits_kernel(const float* __restrict__ H, const float* __restrict__ W,
                              const float* __restrict__ bb, float* __restrict__ out)
{
    int warp = threadIdx.x >> 5, lane = threadIdx.x & 31;
    int row = blockIdx.x * 8 + warp;
    float hv[8];
    #pragma unroll
    for (int j = 0; j < 8; j++) hv[j] = H[(long)row * CHID + j * 32 + lane];
    float acc[CNC];
    #pragma unroll
    for (int c = 0; c < CNC; c++) {
        float a = 0.f;
        #pragma unroll
        for (int j = 0; j < 8; j++) a = fmaf(hv[j], W[(j * 32 + lane) * CNC + c], a);
        acc[c] = a;
    }
    #pragma unroll
    for (int c = 0; c < CNC; c++)
        #pragma unroll
        for (int off = 16; off > 0; off >>= 1)
            acc[c] += __shfl_xor_sync(0xffffffffu, acc[c], off);
    if (lane < CNC) out[(long)row * CNC + lane] = acc[lane] + bb[lane];
}

// ---------------- P_l_1 ----------------
__global__ void pl1_kernel(const float* __restrict__ sadj, const float* __restrict__ P,
                           float* __restrict__ out)
{
    long idx = (long)blockIdx.x * 256 + threadIdx.x;
    int d = idx & (CHID - 1);
    int n = (idx >> 8) & (CN - 1);
    int b = (int)(idx >> 18);
    const float* sa = sadj + (long)b * CM * CN + n;
    const float* Pb = P + (long)b * CM * CHID + d;
    float acc = 0.f;
    #pragma unroll
    for (int m = 0; m < CM; m++) acc = fmaf(sa[m * CN], Pb[m * CHID], acc);
    out[idx] = acc;
}

// ---------------- P_agg ----------------
__global__ void pagg_kernel(const float* __restrict__ sadj, const float* __restrict__ H,
                            float* __restrict__ out)
{
    int bm = blockIdx.x;
    int b = bm >> 3;
    int d = threadIdx.x;
    const float* sa = sadj + (long)bm * CN;
    const float* Hb = H + (long)b * CN * CHID + d;
    float acc = 0.f;
    #pragma unroll 4
    for (int n = 0; n < CN; n++) acc = fmaf(sa[n], Hb[(long)n * CHID], acc);
    out[(long)bm * CHID + d] = acc;
}

// ---------------- e1/e2 dots: warp per row ----------------
__global__ void dots_kernel(const float* __restrict__ h, const float* __restrict__ a1,
                            const float* __restrict__ a2,
                            float* __restrict__ e1, float* __restrict__ e2)
{
    int warp = threadIdx.x >> 5, lane = threadIdx.x & 31;
    int row = blockIdx.x * 8 + warp;
    float s1 = 0.f, s2 = 0.f;
    #pragma unroll
    for (int j = 0; j < 8; j++) {
        int c = j * 32 + lane;
        float v = h[(long)row * CHID + c];
        s1 = fmaf(v, a1[c], s1);
        s2 = fmaf(v, a2[c], s2);
    }
    #pragma unroll
    for (int off = 16; off > 0; off >>= 1) {
        s1 += __shfl_xor_sync(0xffffffffu, s1, off);
        s2 += __shfl_xor_sync(0xffffffffu, s2, off);
    }
    if (lane == 0) { e1[row] = s1; e2[row] = s2; }
}

// ---------------- rel_sc ----------------
__global__ void relsc_kernel(const float* __restrict__ rel, const float* __restrict__ a3,
                             float* __restrict__ out)
{
    __shared__ float s[256];
    int r = blockIdx.x, t = threadIdx.x;
    s[t] = rel[r * CHID + t] * a3[t];
    __syncthreads();
    for (int o = 128; o > 0; o >>= 1) {
        if (t < o) s[t] += s[t + o];
        __syncthreads();
    }
    if (t == 0) out[r] = s[0];
}

// ---------------- GAT edge scores + masked softmax (vectorized) ----------------
__global__ void gat_att_kernel(const float* __restrict__ e1, const float* __restrict__ e2,
                               const float* __restrict__ rsc,
                               const int* __restrict__ adj, const int* __restrict__ smask,
                               float* __restrict__ att)
{
    __shared__ float red[256];
    int bi = blockIdx.x;
    int b = bi >> 10;
    long base = (long)bi * CN;
    int t = threadIdx.x;
    float E1 = e1[bi];
    float r0 = rsc[0], r1 = rsc[1];

    int4   ad = ((const int4*)(adj + base))[t];
    int4   sk = ((const int4*)(smask + base))[t];
    float4 ev = ((const float4*)(e2 + (long)b * CN))[t];

    float vals[4];
    {
        float e;
        e = E1 + ev.x + (sk.x ? r1 : r0); e = e >= 0.f ? e : ALPHAF * e; vals[0] = ad.x ? e : NEGF;
        e = E1 + ev.y + (sk.y ? r1 : r0); e = e >= 0.f ? e : ALPHAF * e; vals[1] = ad.y ? e : NEGF;
        e = E1 + ev.z + (sk.z ? r1 : r0); e = e >= 0.f ? e : ALPHAF * e; vals[2] = ad.z ? e : NEGF;
        e = E1 + ev.w + (sk.w ? r1 : r0); e = e >= 0.f ? e : ALPHAF * e; vals[3] = ad.w ? e : NEGF;
    }
    float mx = fmaxf(fmaxf(vals[0], vals[1]), fmaxf(vals[2], vals[3]));
    red[t] = mx; __syncthreads();
    for (int o = 128; o > 0; o >>= 1) {
        if (t < o) red[t] = fmaxf(red[t], red[t + o]);
        __syncthreads();
    }
    mx = red[0]; __syncthreads();
    float s = 0.f;
    #pragma unroll
    for (int q = 0; q < 4; q++) { vals[q] = expf(vals[q] - mx); s += vals[q]; }
    red[t] = s; __syncthreads();
    for (int o = 128; o > 0; o >>= 1) {
        if (t < o) red[t] += red[t + o];
        __syncthreads();
    }
    float inv = 1.f / red[0];
    ((float4*)(att + base))[t] =
        make_float4(vals[0] * inv, vals[1] * inv, vals[2] * inv, vals[3] * inv);
}

// ---------------- LayerNorm: warp per row ----------------
__global__ void ln_kernel(const float* __restrict__ T, const float* __restrict__ Hold,
                          const float* __restrict__ g, const float* __restrict__ bb,
                          float* __restrict__ out)
{
    int warp = threadIdx.x >> 5, lane = threadIdx.x & 31;
    int row = blockIdx.x * 8 + warp;
    long base = (long)row * CHID;
    float v[8];
    float s = 0.f;
    #pragma unroll
    for (int j = 0; j < 8; j++) {
        int c = j * 32 + lane;
        v[j] = T[base + c] + Hold[base + c];
        s += v[j];
    }
    #pragma unroll
    for (int off = 16; off > 0; off >>= 1) s += __shfl_xor_sync(0xffffffffu, s, off);
    float mu = s * (1.f / CHID);
    float q = 0.f;
    #pragma unroll
    for (int j = 0; j < 8; j++) { v[j] -= mu; q = fmaf(v[j], v[j], q); }
    #pragma unroll
    for (int off = 16; off > 0; off >>= 1) q += __shfl_xor_sync(0xffffffffu, q, off);
    float rstd = rsqrtf(q * (1.f / CHID) + 1e-5f);
    #pragma unroll
    for (int j = 0; j < 8; j++) {
        int c = j * 32 + lane;
        out[base + c] = v[j] * rstd * g[c] + bb[c];
    }
}

// ---------------- GRU3d ----------------
__global__ void gru_kernel(float* __restrict__ P, const float* __restrict__ Pagg,
                           const float* __restrict__ wz, const float* __restrict__ uz,
                           const float* __restrict__ wr, const float* __restrict__ ur,
                           const float* __restrict__ w,  const float* __restrict__ u)
{
    __shared__ float sp[CHID], sq[CHID];
    int r = blockIdx.x;
    int c = threadIdx.x;
    sp[c] = P[(long)r * CHID + c];
    sq[c] = Pagg[(long)r * CHID + c];
    __syncthreads();
    float az = 0, bz = 0, ar = 0, br = 0, aw = 0, bw = 0;
    #pragma unroll 4
    for (int k = 0; k < CHID; k++) {
        float pk = sp[k], qk = sq[k];
        az = fmaf(pk, wz[k * CHID + c], az); bz = fmaf(qk, uz[k * CHID + c], bz);
        ar = fmaf(pk, wr[k * CHID + c], ar); br = fmaf(qk, ur[k * CHID + c], br);
        aw = fmaf(pk, w [k * CHID + c], aw); bw = fmaf(qk, u [k * CHID + c], bw);
    }
    float z  = 1.f / (1.f + expf(-(az + bz)));
    float rr = 1.f / (1.f + expf(-(ar + br)));
    float hh = tanhf(aw + rr * bw);
    P[(long)r * CHID + c] = (1.f - z) * sp[c] + z * hh;
}

// ---------------- p_sim ----------------
__global__ void psim_kernel(const float* __restrict__ P, float* __restrict__ outp, int tail)
{
    __shared__ float red[64];
    int t = threadIdx.x;
    int b = t >> 3, m = t & 7;
    const float* Pb = P + (long)b * CM * CHID;
    float s = 0.f;
    for (int k2 = 0; k2 < CM; k2++) {
        if (k2 == m) continue;
        float d = 0.f;
        for (int dd = 0; dd < CHID; dd++)
            d = fmaf(Pb[m * CHID + dd], Pb[k2 * CHID + dd], d);
        s += d;
    }
    red[t] = s; __syncthreads();
    if ((t & 7) < 4) red[t] += red[t + 4]; __syncthreads();
    if ((t & 7) < 2) red[t] += red[t + 2]; __syncthreads();
    if ((t & 7) < 1) red[t] += red[t + 1]; __syncthreads();
    if (tail >= CB) {
        if (t < CB) outp[t] = red[t * 8] / (float)(CM * CM);
    } else {
        if (t == 0) {
            float tot = 0.f;
            for (int b2 = 0; b2 < CB; b2++) tot += red[b2 * 8];
            outp[0] = tot / (float)(CB * CM * CM);
        }
    }
}

// ---------------- host orchestration ----------------
extern "C" void kernel_launch(void* const* d_in, const int* in_sizes, int n_in,
                              void* d_out, int out_size)
{
    const float* x     = (const float*)d_in[0];
    const int*   adj   = (const int*)  d_in[1];
    const int*   smask = (const int*)  d_in[2];
    const float* sf    = (const float*)d_in[3];
    const float* sadj  = (const float*)d_in[4];
    const float* fc1w  = (const float*)d_in[6];
    const float* fc1b  = (const float*)d_in[7];
    const float* fc2w  = (const float*)d_in[8];
    const float* fc2b  = (const float*)d_in[9];
    const float* gatW  = (const float*)d_in[10];
    const float* gata  = (const float*)d_in[11];
    const float* rel   = (const float*)d_in[12];
    const float* gwz   = (const float*)d_in[13];
    const float* guz   = (const float*)d_in[14];
    const float* gwr   = (const float*)d_in[15];
    const float* gur   = (const float*)d_in[16];
    const float* gw    = (const float*)d_in[17];
    const float* gu    = (const float*)d_in[18];
    const float* wv    = (const float*)d_in[19];
    const float* bv    = (const float*)d_in[20];
    const float* wk    = (const float*)d_in[21];
    const float* bk    = (const float*)d_in[22];
    const float* wq    = (const float*)d_in[23];
    const float* bq    = (const float*)d_in[24];
    const float* wo    = (const float*)d_in[25];
    const float* bo    = (const float*)d_in[26];
    const float* lng   = (const float*)d_in[27];
    const float* lnb   = (const float*)d_in[28];
    const float* outw  = (const float*)d_in[29];
    const float* outb  = (const float*)d_in[30];
    float* out = (float*)d_out;

    float *H, *Hn, *P, *Pagg, *Pl1, *hb, *Agg, *Qb, *Kb, *Vb, *ctx, *Tb, *att, *e1, *e2, *rsc;
    cudaGetSymbolAddress((void**)&H,    g_H);
    cudaGetSymbolAddress((void**)&Hn,   g_Hn);
    cudaGetSymbolAddress((void**)&P,    g_P);
    cudaGetSymbolAddress((void**)&Pagg, g_Pagg);
    cudaGetSymbolAddress((void**)&Pl1,  g_Pl1);
    cudaGetSymbolAddress((void**)&hb,   g_h);
    cudaGetSymbolAddress((void**)&Agg,  g_Agg);
    cudaGetSymbolAddress((void**)&Qb,   g_Q);
    cudaGetSymbolAddress((void**)&Kb,   g_K);
    cudaGetSymbolAddress((void**)&Vb,   g_V);
    cudaGetSymbolAddress((void**)&ctx,  g_ctx);
    cudaGetSymbolAddress((void**)&Tb,   g_T);
    cudaGetSymbolAddress((void**)&att,  g_att);
    cudaGetSymbolAddress((void**)&e1,   g_e1);
    cudaGetSymbolAddress((void**)&e2,   g_e2);
    cudaGetSymbolAddress((void**)&rsc,  g_rsc);

    cudaFuncSetAttribute(tgemm<0>, cudaFuncAttributeMaxDynamicSharedMemorySize, SM_TG);
    cudaFuncSetAttribute(tgemm<1>, cudaFuncAttributeMaxDynamicSharedMemorySize, SM_TG);
    cudaFuncSetAttribute(tgemm<2>, cudaFuncAttributeMaxDynamicSharedMemorySize, SM_TG);
    cudaFuncSetAttribute(tgemm_pair, cudaFuncAttributeMaxDynamicSharedMemorySize, SM_TG);
    cudaFuncSetAttribute(flash_kernel, cudaFuncAttributeMaxDynamicSharedMemorySize, SM_FLASH);

    dim3 blk(256);
    const int BN = CB * CN;                          // 8192
    const long HH = (long)CHID * CHID;               // 65536

    // H = relu(x @ fc1_w + b)
    tgemm<1><<<dim3(2, 64, 1), blk, SM_TG>>>(x, fc1w, fc1b, H, BN, CHID, CDIN, 0, 0, 0, 1.f);
    // P = relu(s_feature @ fc2_w + b)
    sgemm<1><<<dim3(4, 1, 1), blk>>>(sf, fc2w, fc2b, P, CB * CM, CHID, CDIN);

    for (int l = 0; l < CL; l++) {
        float* cur = l ? Hn : H;
        float* nxt = l ? H : Hn;

        // P_l_1 = s_adj^T @ P
        pl1_kernel<<<BN * CHID / 256, blk>>>(sadj, P, Pl1);

        // paired: h = cur @ gat_W[l] ; V = cur @ wv + bv
        {
            G2 a;
            a.A[0] = cur;           a.A[1] = cur;
            a.B[0] = gatW + l * HH; a.B[1] = wv + l * HH;
            a.bias[0] = nullptr;    a.bias[1] = bv + l * CHID;
            a.C[0] = hb;            a.C[1] = Vb;
            tgemm_pair<<<dim3(2, 64, 2), blk, SM_TG>>>(a, BN, CHID, CHID);
        }
        // edge-score ingredients
        dots_kernel<<<BN / 8, blk>>>(hb, gata + l * 3 * CHID, gata + l * 3 * CHID + CHID, e1, e2);
        relsc_kernel<<<2, blk>>>(rel + l * 2 * CHID, gata + l * 3 * CHID + 2 * CHID, rsc);
        gat_att_kernel<<<BN, blk>>>(e1, e2, rsc, adj, smask, att);
        // Agg = elu(att @ h)
        tgemm<2><<<dim3(2, 8, CB), blk, SM_TG>>>(att, hb, nullptr, Agg,
                                                 CN, CHID, CN,
                                                 (long)CN * CN, (long)CN * CHID, (long)CN * CHID, 1.f);
        // paired: K = Pl1 @ wk + bk ; Q = Agg @ wq + bq
        {
            G2 a;
            a.A[0] = Pl1;           a.A[1] = Agg;
            a.B[0] = wk + l * HH;   a.B[1] = wq + l * HH;
            a.bias[0] = bk + l * CHID; a.bias[1] = bq + l * CHID;
            a.C[0] = Kb;            a.C[1] = Qb;
            tgemm_pair<<<dim3(2, 64, 2), blk, SM_TG>>>(a, BN, CHID, CHID);
        }
        // fused MHA
        flash_kernel<<<dim3(8, 32), blk, SM_FLASH>>>(Qb, Kb, Vb, ctx);
        // T = ctx @ wo + bo ;  H_new = LN(T + H)
        tgemm<0><<<dim3(2, 64, 1), blk, SM_TG>>>(ctx, wo + l * HH, bo + l * CHID, Tb,
                                                 BN, CHID, CHID, 0, 0, 0, 1.f);
        ln_kernel<<<BN / 8, blk>>>(Tb, cur, lng + l * CHID, lnb + l * CHID, nxt);

        // GRU speaker update (uses pre-update H)
        pagg_kernel<<<CB * CM, blk>>>(sadj, cur, Pagg);
        gru_kernel<<<CB * CM, blk>>>(P, Pagg,
                                     gwz + l * HH, guz + l * HH,
                                     gwr + l * HH, gur + l * HH,
                                     gw + l * HH,  gu + l * HH);
    }

    // logits
    logits_kernel<<<BN / 8, blk>>>(H, outw, outb, out);
    // p_sim
    psim_kernel<<<1, 64>>>(P, out + (long)BN * CNC, out_size - BN * CNC);
}